// round 1
// baseline (speedup 1.0000x reference)
#include <cuda_runtime.h>
#include <cuda_bf16.h>
#include <math.h>

// Problem constants
#define N_TOK   8192
#define DDIM    1024
#define FDIM    4096
#define NEXP    8
#define CAP     1280          // int(8192/8 * 1.25)
#define SLOTS_PER_E (2*CAP)   // 2560 (k=0 segment [0,1280), k=1 segment [1280,2560))
#define TOT_SLOTS (NEXP*SLOTS_PER_E)

// ---------------- scratch (static __device__, no runtime allocs) ----------------
__device__ float g_hg[(size_t)NEXP*SLOTS_PER_E*FDIM];   // gate pre-act, later act
__device__ float g_hu[(size_t)NEXP*SLOTS_PER_E*FDIM];   // up
__device__ float g_ybuf[(size_t)N_TOK*2*DDIM];          // per-(token,k) expert output (scaled)
__device__ int   g_tok[TOT_SLOTS];                      // slot -> token id (-1 = empty)
__device__ float g_wgt[TOT_SLOTS];                      // slot -> combine weight
__device__ int   g_eids[N_TOK*2];
__device__ float g_ew[N_TOK*2];
__device__ float g_probs[N_TOK*NEXP];
__device__ float g_lse[N_TOK];
__device__ int   g_rank[2*N_TOK];                       // exclusive rank within (k, expert) stream
__device__ int   g_cnt[2*NEXP];                         // raw counts per (k, expert)

// ---------------- router: logits, softmax, top-2, weights ----------------
__global__ void __launch_bounds__(256) router_kernel(const float* __restrict__ x,
                                                     const float* __restrict__ gw)
{
    int t = blockIdx.x;
    const float* xr = x + (size_t)t * DDIM;
    __shared__ float sred[NEXP][256];
    float acc[NEXP];
#pragma unroll
    for (int e = 0; e < NEXP; e++) acc[e] = 0.f;
    for (int d = threadIdx.x; d < DDIM; d += 256) {
        float xv = xr[d];
#pragma unroll
        for (int e = 0; e < NEXP; e++) acc[e] += xv * gw[e*DDIM + d];
    }
#pragma unroll
    for (int e = 0; e < NEXP; e++) sred[e][threadIdx.x] = acc[e];
    __syncthreads();
    for (int s = 128; s > 0; s >>= 1) {
        if (threadIdx.x < s) {
#pragma unroll
            for (int e = 0; e < NEXP; e++) sred[e][threadIdx.x] += sred[e][threadIdx.x + s];
        }
        __syncthreads();
    }
    if (threadIdx.x == 0) {
        float lg[NEXP];
#pragma unroll
        for (int e = 0; e < NEXP; e++) lg[e] = sred[e][0];
        float mx = lg[0];
#pragma unroll
        for (int e = 1; e < NEXP; e++) mx = fmaxf(mx, lg[e]);
        float se = 0.f, p[NEXP];
#pragma unroll
        for (int e = 0; e < NEXP; e++) { p[e] = expf(lg[e] - mx); se += p[e]; }
        float inv = 1.f / se;
#pragma unroll
        for (int e = 0; e < NEXP; e++) { p[e] *= inv; g_probs[t*NEXP + e] = p[e]; }
        g_lse[t] = mx + logf(se);
        // top-2 (ties -> lowest index, matching jax.lax.top_k)
        int i0 = 0;
#pragma unroll
        for (int e = 1; e < NEXP; e++) if (p[e] > p[i0]) i0 = e;
        int i1 = -1;
#pragma unroll
        for (int e = 0; e < NEXP; e++) {
            if (e == i0) continue;
            if (i1 < 0 || p[e] > p[i1]) i1 = e;
        }
        float s2 = p[i0] + p[i1];
        g_eids[t*2 + 0] = i0; g_eids[t*2 + 1] = i1;
        g_ew[t*2 + 0] = p[i0] / s2; g_ew[t*2 + 1] = p[i1] / s2;
    }
}

// ---------------- rank: exclusive prefix count per (k, expert) in token order ----------------
__global__ void __launch_bounds__(256) rank_kernel()
{
    int k = blockIdx.x >> 3;
    int e = blockIdx.x & 7;
    __shared__ int warp_sums[8];
    __shared__ int s_base;
    if (threadIdx.x == 0) s_base = 0;
    __syncthreads();
    int lane = threadIdx.x & 31, wid = threadIdx.x >> 5;
    for (int c = 0; c < N_TOK; c += 256) {
        int t = c + threadIdx.x;
        int flag = (g_eids[t*2 + k] == e) ? 1 : 0;
        unsigned m = __ballot_sync(0xffffffffu, flag);
        int pre = __popc(m & ((1u << lane) - 1u));
        if (lane == 31) warp_sums[wid] = pre + flag;
        __syncthreads();
        int wbase = 0;
        for (int w = 0; w < wid; w++) wbase += warp_sums[w];
        if (flag) g_rank[k*N_TOK + t] = s_base + wbase + pre;
        __syncthreads();
        if (threadIdx.x == 0) {
            int tot = 0;
            for (int w = 0; w < 8; w++) tot += warp_sums[w];
            s_base += tot;
        }
        __syncthreads();
    }
    if (threadIdx.x == 0) g_cnt[k*NEXP + e] = s_base;
}

// ---------------- clear token slots ----------------
__global__ void clear_tok_kernel()
{
    int i = blockIdx.x * 256 + threadIdx.x;
    if (i < TOT_SLOTS) { g_tok[i] = -1; g_wgt[i] = 0.f; }
}

// ---------------- build compact per-expert lists ----------------
__global__ void build_kernel()
{
    int t = blockIdx.x * 256 + threadIdx.x;
    if (t >= N_TOK) return;
#pragma unroll
    for (int k = 0; k < 2; k++) {
        int e = g_eids[t*2 + k];
        int r = g_rank[k*N_TOK + t];
        if (r < CAP) {
            int slot = e*SLOTS_PER_E + k*CAP + r;
            g_tok[slot] = t;
            g_wgt[slot] = g_ew[t*2 + k];
        }
    }
}

// ---------------- GEMM1: h = X_gathered @ W^T  (K = DDIM) ----------------
// grid: (FDIM/128, SLOTS_PER_E/128, NEXP*2), block 256
__global__ void __launch_bounds__(256) gemm1_kernel(const float* __restrict__ x,
                                                    const float* __restrict__ wi_gate,
                                                    const float* __restrict__ wi_up)
{
    int e = blockIdx.z >> 1;
    int which = blockIdx.z & 1;
    int m0 = blockIdx.y * 128;
    int seg = (m0 >= CAP) ? 1 : 0;
    int lim = min(g_cnt[seg*NEXP + e], CAP);
    if ((m0 - seg*CAP) >= lim) return;

    const float* W = (which ? wi_up : wi_gate) + (size_t)e * FDIM * DDIM;
    float* C = (which ? g_hu : g_hg) + (size_t)e * SLOTS_PER_E * FDIM;
    int n0 = blockIdx.x * 128;

    __shared__ float As[8][128];
    __shared__ float Bs[8][128];
    __shared__ int stok[128];

    int tid = threadIdx.x;
    if (tid < 128) stok[tid] = g_tok[e*SLOTS_PER_E + m0 + tid];
    __syncthreads();

    int arow = tid >> 1;
    int acol = (tid & 1) << 2;
    int tokr = stok[arow];
    const float* abase = x + ((tokr >= 0) ? ((size_t)tokr * DDIM + acol) : 0);
    const float* wbase = W + (size_t)(n0 + arow) * DDIM + acol;

    float acc[8][8];
#pragma unroll
    for (int i = 0; i < 8; i++)
#pragma unroll
        for (int j = 0; j < 8; j++) acc[i][j] = 0.f;

    int tx = tid & 15, ty = tid >> 4;

    for (int k0 = 0; k0 < DDIM; k0 += 8) {
        float4 av = make_float4(0.f, 0.f, 0.f, 0.f);
        if (tokr >= 0) av = *(const float4*)(abase + k0);
        float4 wv = *(const float4*)(wbase + k0);
        As[acol+0][arow] = av.x; As[acol+1][arow] = av.y;
        As[acol+2][arow] = av.z; As[acol+3][arow] = av.w;
        Bs[acol+0][arow] = wv.x; Bs[acol+1][arow] = wv.y;
        Bs[acol+2][arow] = wv.z; Bs[acol+3][arow] = wv.w;
        __syncthreads();
#pragma unroll
        for (int kk = 0; kk < 8; kk++) {
            float a[8], b[8];
            *(float4*)(a)     = *(const float4*)&As[kk][ty*4];
            *(float4*)(a + 4) = *(const float4*)&As[kk][64 + ty*4];
            *(float4*)(b)     = *(const float4*)&Bs[kk][tx*4];
            *(float4*)(b + 4) = *(const float4*)&Bs[kk][64 + tx*4];
#pragma unroll
            for (int i = 0; i < 8; i++)
#pragma unroll
                for (int j = 0; j < 8; j++) acc[i][j] += a[i] * b[j];
        }
        __syncthreads();
    }
#pragma unroll
    for (int i = 0; i < 8; i++) {
        int r = (i < 4) ? (ty*4 + i) : (64 + ty*4 + (i - 4));
        float* crow = C + (size_t)(m0 + r) * FDIM + n0;
        *(float4*)(crow + tx*4)      = make_float4(acc[i][0], acc[i][1], acc[i][2], acc[i][3]);
        *(float4*)(crow + 64 + tx*4) = make_float4(acc[i][4], acc[i][5], acc[i][6], acc[i][7]);
    }
}

// ---------------- activation: act = silu(hg) * hu (in-place into hg) ----------------
__global__ void __launch_bounds__(256) act_kernel()
{
    size_t idx = (size_t)blockIdx.x * 256 + threadIdx.x;     // float4 index
    int slot = (int)(idx >> 10);                              // FDIM/4 = 1024 v4 per row
    if (g_tok[slot] < 0) return;
    float4 g = ((const float4*)g_hg)[idx];
    float4 u = ((const float4*)g_hu)[idx];
    g.x = g.x / (1.f + expf(-g.x)) * u.x;
    g.y = g.y / (1.f + expf(-g.y)) * u.y;
    g.z = g.z / (1.f + expf(-g.z)) * u.z;
    g.w = g.w / (1.f + expf(-g.w)) * u.w;
    ((float4*)g_hg)[idx] = g;
}

// ---------------- GEMM2: y = act @ Wo^T  (K = FDIM), scaled scatter to ybuf ----------------
// grid: (DDIM/128, SLOTS_PER_E/128, NEXP), block 256
__global__ void __launch_bounds__(256) gemm2_kernel(const float* __restrict__ wo)
{
    int e = blockIdx.z;
    int m0 = blockIdx.y * 128;
    int seg = (m0 >= CAP) ? 1 : 0;
    int lim = min(g_cnt[seg*NEXP + e], CAP);
    if ((m0 - seg*CAP) >= lim) return;

    const float* W = wo + (size_t)e * DDIM * FDIM;
    const float* A = g_hg + (size_t)e * SLOTS_PER_E * FDIM;
    int n0 = blockIdx.x * 128;

    __shared__ float As[8][128];
    __shared__ float Bs[8][128];
    __shared__ int   stok[128];
    __shared__ float swgt[128];

    int tid = threadIdx.x;
    if (tid < 128) {
        stok[tid] = g_tok[e*SLOTS_PER_E + m0 + tid];
        swgt[tid] = g_wgt[e*SLOTS_PER_E + m0 + tid];
    }
    __syncthreads();

    int arow = tid >> 1;
    int acol = (tid & 1) << 2;
    const float* abase = A + (size_t)(m0 + arow) * FDIM + acol;
    const float* wbase = W + (size_t)(n0 + arow) * FDIM + acol;

    float acc[8][8];
#pragma unroll
    for (int i = 0; i < 8; i++)
#pragma unroll
        for (int j = 0; j < 8; j++) acc[i][j] = 0.f;

    int tx = tid & 15, ty = tid >> 4;

    for (int k0 = 0; k0 < FDIM; k0 += 8) {
        float4 av = *(const float4*)(abase + k0);
        float4 wv = *(const float4*)(wbase + k0);
        As[acol+0][arow] = av.x; As[acol+1][arow] = av.y;
        As[acol+2][arow] = av.z; As[acol+3][arow] = av.w;
        Bs[acol+0][arow] = wv.x; Bs[acol+1][arow] = wv.y;
        Bs[acol+2][arow] = wv.z; Bs[acol+3][arow] = wv.w;
        __syncthreads();
#pragma unroll
        for (int kk = 0; kk < 8; kk++) {
            float a[8], b[8];
            *(float4*)(a)     = *(const float4*)&As[kk][ty*4];
            *(float4*)(a + 4) = *(const float4*)&As[kk][64 + ty*4];
            *(float4*)(b)     = *(const float4*)&Bs[kk][tx*4];
            *(float4*)(b + 4) = *(const float4*)&Bs[kk][64 + tx*4];
#pragma unroll
            for (int i = 0; i < 8; i++)
#pragma unroll
                for (int j = 0; j < 8; j++) acc[i][j] += a[i] * b[j];
        }
        __syncthreads();
    }
#pragma unroll
    for (int i = 0; i < 8; i++) {
        int r = (i < 4) ? (ty*4 + i) : (64 + ty*4 + (i - 4));
        int t = stok[r];
        if (t < 0) continue;
        float w = swgt[r];
        float* orow = g_ybuf + ((size_t)t * 2 + seg) * DDIM + n0;
        *(float4*)(orow + tx*4) =
            make_float4(acc[i][0]*w, acc[i][1]*w, acc[i][2]*w, acc[i][3]*w);
        *(float4*)(orow + 64 + tx*4) =
            make_float4(acc[i][4]*w, acc[i][5]*w, acc[i][6]*w, acc[i][7]*w);
    }
}

// ---------------- combine: out[t] = ybuf[t,0] + ybuf[t,1] (validity-masked) ----------------
__global__ void __launch_bounds__(256) combine_kernel(float* __restrict__ out)
{
    int t = blockIdx.x;
    bool v0 = g_rank[t] < CAP;
    bool v1 = g_rank[N_TOK + t] < CAP;
    const float4* y0 = (const float4*)(g_ybuf + (size_t)t * 2 * DDIM);
    const float4* y1 = y0 + DDIM/4;
    float4 a = v0 ? y0[threadIdx.x] : make_float4(0.f,0.f,0.f,0.f);
    float4 b = v1 ? y1[threadIdx.x] : make_float4(0.f,0.f,0.f,0.f);
    float4 r = make_float4(a.x+b.x, a.y+b.y, a.z+b.z, a.w+b.w);
    ((float4*)(out + (size_t)t * DDIM))[threadIdx.x] = r;
}

// ---------------- aux loss: deterministic tree reduction ----------------
__global__ void __launch_bounds__(1024) aux_kernel(float* __restrict__ out_aux)
{
    __shared__ float sb[1024];
    __shared__ float res[9];
    int tid = threadIdx.x;
    float pacc[NEXP];
#pragma unroll
    for (int e = 0; e < NEXP; e++) pacc[e] = 0.f;
    float zacc = 0.f;
    for (int i = 0; i < N_TOK/1024; i++) {
        int t = tid * (N_TOK/1024) + i;
        const float* pr = g_probs + (size_t)t * NEXP;
#pragma unroll
        for (int e = 0; e < NEXP; e++) pacc[e] += pr[e];
        float l = g_lse[t];
        zacc += l * l;
    }
    for (int e = 0; e < NEXP; e++) {
        sb[tid] = pacc[e];
        __syncthreads();
        for (int s = 512; s > 0; s >>= 1) {
            if (tid < s) sb[tid] += sb[tid + s];
            __syncthreads();
        }
        if (tid == 0) res[e] = sb[0];
        __syncthreads();
    }
    sb[tid] = zacc;
    __syncthreads();
    for (int s = 512; s > 0; s >>= 1) {
        if (tid < s) sb[tid] += sb[tid + s];
        __syncthreads();
    }
    if (tid == 0) res[8] = sb[0];
    __syncthreads();
    if (tid == 0) {
        float lb = 0.f;
#pragma unroll
        for (int e = 0; e < NEXP; e++) {
            float density = (float)(g_cnt[e] + g_cnt[NEXP + e]) / (float)(N_TOK * 2);
            float mean_p = res[e] / (float)N_TOK;
            lb += density * mean_p;
        }
        lb *= 0.01f * (float)NEXP;
        float z = 0.001f * (res[8] / (float)N_TOK);
        out_aux[0] = lb + z;
    }
}

// ---------------- launch ----------------
extern "C" void kernel_launch(void* const* d_in, const int* in_sizes, int n_in,
                              void* d_out, int out_size)
{
    const float* x       = (const float*)d_in[0];
    const float* gate_w  = (const float*)d_in[1];
    const float* wi_gate = (const float*)d_in[2];
    const float* wi_up   = (const float*)d_in[3];
    const float* wo      = (const float*)d_in[4];
    float* out = (float*)d_out;

    clear_tok_kernel<<<(TOT_SLOTS + 255)/256, 256>>>();
    router_kernel<<<N_TOK, 256>>>(x, gate_w);
    rank_kernel<<<16, 256>>>();
    build_kernel<<<N_TOK/256, 256>>>();

    gemm1_kernel<<<dim3(FDIM/128, SLOTS_PER_E/128, NEXP*2), 256>>>(x, wi_gate, wi_up);

    size_t n_v4 = (size_t)NEXP * SLOTS_PER_E * FDIM / 4;
    act_kernel<<<(unsigned)(n_v4 / 256), 256>>>();

    gemm2_kernel<<<dim3(DDIM/128, SLOTS_PER_E/128, NEXP), 256>>>(wo);

    combine_kernel<<<N_TOK, 256>>>(out);

    if (out_size > N_TOK * DDIM) {
        aux_kernel<<<1, 1024>>>(out + (size_t)N_TOK * DDIM);
    }
}

// round 2
// speedup vs baseline: 2.6752x; 2.6752x over previous
#include <cuda_runtime.h>
#include <cuda_bf16.h>
#include <math.h>

// Problem constants
#define N_TOK   8192
#define DDIM    1024
#define FDIM    4096
#define NEXP    8
#define CAP     1280          // int(8192/8 * 1.25)
#define SLOTS_PER_E (2*CAP)   // 2560 (k=0 segment [0,1280), k=1 segment [1280,2560))
#define TOT_SLOTS (NEXP*SLOTS_PER_E)

// GEMM tiling
#define STAGES  4
#define BK      16
#define ASTRIDE 20                 // floats per smem row (16 + 4 pad)
#define A_STAGE (128*ASTRIDE)      // floats per stage per operand
#define SMEM_BYTES (STAGES*2*A_STAGE*4)   // 81920

// ---------------- scratch (static __device__, no runtime allocs) ----------------
__device__ float g_hg[(size_t)NEXP*SLOTS_PER_E*FDIM];   // gate pre-act, later act
__device__ float g_hu[(size_t)NEXP*SLOTS_PER_E*FDIM];   // up
__device__ float g_ybuf[(size_t)N_TOK*2*DDIM];          // per-(token,k) expert output (scaled)
__device__ int   g_tok[TOT_SLOTS];                      // slot -> token id (-1 = empty)
__device__ float g_wgt[TOT_SLOTS];                      // slot -> combine weight
__device__ int   g_eids[N_TOK*2];
__device__ float g_ew[N_TOK*2];
__device__ float g_probs[N_TOK*NEXP];
__device__ float g_lse[N_TOK];
__device__ int   g_rank[2*N_TOK];                       // exclusive rank within (k, expert) stream
__device__ int   g_cnt[2*NEXP];                         // raw counts per (k, expert)

// ---------------- helpers ----------------
__device__ __forceinline__ void cp_async16(float* dst, const float* src, int bytes)
{
    unsigned s = (unsigned)__cvta_generic_to_shared(dst);
    asm volatile("cp.async.ca.shared.global [%0], [%1], 16, %2;\n"
                 :: "r"(s), "l"(src), "r"(bytes));
}
__device__ __forceinline__ void cp_commit() { asm volatile("cp.async.commit_group;\n"); }
__device__ __forceinline__ void cp_wait()   { asm volatile("cp.async.wait_group %0;\n" :: "n"(STAGES-2)); }

__device__ __forceinline__ unsigned f2tf(float f)
{
    unsigned u;
    asm("cvt.rna.tf32.f32 %0, %1;\n" : "=r"(u) : "f"(f));
    return u;
}

__device__ __forceinline__ void mma_tf32(float* c, const unsigned* a, const unsigned* b)
{
    asm volatile(
        "mma.sync.aligned.m16n8k8.row.col.f32.tf32.tf32.f32 "
        "{%0,%1,%2,%3}, {%4,%5,%6,%7}, {%8,%9}, {%0,%1,%2,%3};\n"
        : "+f"(c[0]), "+f"(c[1]), "+f"(c[2]), "+f"(c[3])
        : "r"(a[0]), "r"(a[1]), "r"(a[2]), "r"(a[3]), "r"(b[0]), "r"(b[1]));
}

// ---------------- router: logits, softmax, top-2, weights ----------------
__global__ void __launch_bounds__(256) router_kernel(const float* __restrict__ x,
                                                     const float* __restrict__ gw)
{
    int t = blockIdx.x;
    const float* xr = x + (size_t)t * DDIM;
    __shared__ float sred[NEXP][256];
    float acc[NEXP];
#pragma unroll
    for (int e = 0; e < NEXP; e++) acc[e] = 0.f;
    for (int d = threadIdx.x; d < DDIM; d += 256) {
        float xv = xr[d];
#pragma unroll
        for (int e = 0; e < NEXP; e++) acc[e] += xv * gw[e*DDIM + d];
    }
#pragma unroll
    for (int e = 0; e < NEXP; e++) sred[e][threadIdx.x] = acc[e];
    __syncthreads();
    for (int s = 128; s > 0; s >>= 1) {
        if (threadIdx.x < s) {
#pragma unroll
            for (int e = 0; e < NEXP; e++) sred[e][threadIdx.x] += sred[e][threadIdx.x + s];
        }
        __syncthreads();
    }
    if (threadIdx.x == 0) {
        float lg[NEXP];
#pragma unroll
        for (int e = 0; e < NEXP; e++) lg[e] = sred[e][0];
        float mx = lg[0];
#pragma unroll
        for (int e = 1; e < NEXP; e++) mx = fmaxf(mx, lg[e]);
        float se = 0.f, p[NEXP];
#pragma unroll
        for (int e = 0; e < NEXP; e++) { p[e] = expf(lg[e] - mx); se += p[e]; }
        float inv = 1.f / se;
#pragma unroll
        for (int e = 0; e < NEXP; e++) { p[e] *= inv; g_probs[t*NEXP + e] = p[e]; }
        g_lse[t] = mx + logf(se);
        int i0 = 0;
#pragma unroll
        for (int e = 1; e < NEXP; e++) if (p[e] > p[i0]) i0 = e;
        int i1 = -1;
#pragma unroll
        for (int e = 0; e < NEXP; e++) {
            if (e == i0) continue;
            if (i1 < 0 || p[e] > p[i1]) i1 = e;
        }
        float s2 = p[i0] + p[i1];
        g_eids[t*2 + 0] = i0; g_eids[t*2 + 1] = i1;
        g_ew[t*2 + 0] = p[i0] / s2; g_ew[t*2 + 1] = p[i1] / s2;
    }
}

// ---------------- rank: exclusive prefix count per (k, expert) in token order ----------------
__global__ void __launch_bounds__(256) rank_kernel()
{
    int k = blockIdx.x >> 3;
    int e = blockIdx.x & 7;
    __shared__ int warp_sums[8];
    __shared__ int s_base;
    if (threadIdx.x == 0) s_base = 0;
    __syncthreads();
    int lane = threadIdx.x & 31, wid = threadIdx.x >> 5;
    for (int c = 0; c < N_TOK; c += 256) {
        int t = c + threadIdx.x;
        int flag = (g_eids[t*2 + k] == e) ? 1 : 0;
        unsigned m = __ballot_sync(0xffffffffu, flag);
        int pre = __popc(m & ((1u << lane) - 1u));
        if (lane == 31) warp_sums[wid] = pre + flag;
        __syncthreads();
        int wbase = 0;
        for (int w = 0; w < wid; w++) wbase += warp_sums[w];
        if (flag) g_rank[k*N_TOK + t] = s_base + wbase + pre;
        __syncthreads();
        if (threadIdx.x == 0) {
            int tot = 0;
            for (int w = 0; w < 8; w++) tot += warp_sums[w];
            s_base += tot;
        }
        __syncthreads();
    }
    if (threadIdx.x == 0) g_cnt[k*NEXP + e] = s_base;
}

// ---------------- clear token slots ----------------
__global__ void clear_tok_kernel()
{
    int i = blockIdx.x * 256 + threadIdx.x;
    if (i < TOT_SLOTS) { g_tok[i] = -1; g_wgt[i] = 0.f; }
}

// ---------------- build compact per-expert lists ----------------
__global__ void build_kernel()
{
    int t = blockIdx.x * 256 + threadIdx.x;
    if (t >= N_TOK) return;
#pragma unroll
    for (int k = 0; k < 2; k++) {
        int e = g_eids[t*2 + k];
        int r = g_rank[k*N_TOK + t];
        if (r < CAP) {
            int slot = e*SLOTS_PER_E + k*CAP + r;
            g_tok[slot] = t;
            g_wgt[slot] = g_ew[t*2 + k];
        }
    }
}

// ---------------- GEMM1 (tf32 mma): h = X_gathered @ W^T, K = DDIM ----------------
// grid: (FDIM/128, SLOTS_PER_E/128, NEXP*2), block 256, dyn smem
__global__ void __launch_bounds__(256, 2) gemm1_mma(const float* __restrict__ x,
                                                    const float* __restrict__ wi_gate,
                                                    const float* __restrict__ wi_up)
{
    int e = blockIdx.z >> 1;
    int which = blockIdx.z & 1;
    int m0 = blockIdx.y * 128;
    int seg = (m0 >= CAP) ? 1 : 0;
    int lim = min(g_cnt[seg*NEXP + e], CAP);
    if ((m0 - seg*CAP) >= lim) return;

    const float* W = (which ? wi_up : wi_gate) + (size_t)e * FDIM * DDIM;
    float* C = (which ? g_hu : g_hg) + (size_t)e * SLOTS_PER_E * FDIM;
    int n0 = blockIdx.x * 128;

    extern __shared__ float sm[];
    float* sA = sm;
    float* sB = sm + STAGES*A_STAGE;

    int tid = threadIdx.x;
    int ar = tid >> 2;
    int ac = (tid & 3) << 2;
    int slotbase = e*SLOTS_PER_E + m0;
    int tok0 = g_tok[slotbase + ar];
    int tok1 = g_tok[slotbase + ar + 64];
    const float* ap0 = x + (size_t)max(tok0, 0) * DDIM + ac;
    const float* ap1 = x + (size_t)max(tok1, 0) * DDIM + ac;
    int sz0 = (tok0 >= 0) ? 16 : 0;
    int sz1 = (tok1 >= 0) ? 16 : 0;
    const float* bp0 = W + (size_t)(n0 + ar) * DDIM + ac;
    const float* bp1 = W + (size_t)(n0 + ar + 64) * DDIM + ac;

    const int KT = DDIM / BK;   // 64

#pragma unroll
    for (int s = 0; s < STAGES-1; s++) {
        float* dA = sA + s*A_STAGE;
        float* dB = sB + s*A_STAGE;
        int k0 = s * BK;
        cp_async16(dA + ar*ASTRIDE + ac,        ap0 + k0, sz0);
        cp_async16(dA + (ar+64)*ASTRIDE + ac,   ap1 + k0, sz1);
        cp_async16(dB + ar*ASTRIDE + ac,        bp0 + k0, 16);
        cp_async16(dB + (ar+64)*ASTRIDE + ac,   bp1 + k0, 16);
        cp_commit();
    }

    float acc[4][4][4];
#pragma unroll
    for (int a = 0; a < 4; a++)
#pragma unroll
        for (int b = 0; b < 4; b++)
#pragma unroll
            for (int c = 0; c < 4; c++) acc[a][b][c] = 0.f;

    int wid = tid >> 5, lane = tid & 31;
    int wm = wid & 1, wn = wid >> 1;
    int g = lane >> 2, tg = lane & 3;

    for (int kt = 0; kt < KT; kt++) {
        cp_wait();
        __syncthreads();
        int pf = kt + STAGES - 1;
        if (pf < KT) {
            int st = pf % STAGES;
            float* dA = sA + st*A_STAGE;
            float* dB = sB + st*A_STAGE;
            int k0 = pf * BK;
            cp_async16(dA + ar*ASTRIDE + ac,      ap0 + k0, sz0);
            cp_async16(dA + (ar+64)*ASTRIDE + ac, ap1 + k0, sz1);
            cp_async16(dB + ar*ASTRIDE + ac,      bp0 + k0, 16);
            cp_async16(dB + (ar+64)*ASTRIDE + ac, bp1 + k0, 16);
        }
        cp_commit();
        const float* a_s = sA + (kt % STAGES)*A_STAGE;
        const float* b_s = sB + (kt % STAGES)*A_STAGE;
#pragma unroll
        for (int kk = 0; kk < BK; kk += 8) {
            unsigned af[4][4], bf[4][2];
#pragma unroll
            for (int mt = 0; mt < 4; mt++) {
                int r = wm*64 + mt*16 + g;
                const float* p = a_s + r*ASTRIDE + kk + tg;
                af[mt][0] = f2tf(p[0]);
                af[mt][1] = f2tf(p[8*ASTRIDE]);
                af[mt][2] = f2tf(p[4]);
                af[mt][3] = f2tf(p[8*ASTRIDE + 4]);
            }
#pragma unroll
            for (int nt = 0; nt < 4; nt++) {
                int n = wn*32 + nt*8 + g;
                const float* p = b_s + n*ASTRIDE + kk + tg;
                bf[nt][0] = f2tf(p[0]);
                bf[nt][1] = f2tf(p[4]);
            }
#pragma unroll
            for (int mt = 0; mt < 4; mt++)
#pragma unroll
                for (int nt = 0; nt < 4; nt++)
                    mma_tf32(acc[mt][nt], af[mt], bf[nt]);
        }
    }

#pragma unroll
    for (int mt = 0; mt < 4; mt++) {
        int r0 = m0 + wm*64 + mt*16 + g;
#pragma unroll
        for (int nt = 0; nt < 4; nt++) {
            int c0 = n0 + wn*32 + nt*8 + tg*2;
            float2 v0 = make_float2(acc[mt][nt][0], acc[mt][nt][1]);
            float2 v1 = make_float2(acc[mt][nt][2], acc[mt][nt][3]);
            *(float2*)&C[(size_t)r0*FDIM + c0]     = v0;
            *(float2*)&C[(size_t)(r0+8)*FDIM + c0] = v1;
        }
    }
}

// ---------------- activation: act = silu(hg) * hu (in-place into hg) ----------------
__global__ void __launch_bounds__(256) act_kernel()
{
    size_t idx = (size_t)blockIdx.x * 256 + threadIdx.x;     // float4 index
    int slot = (int)(idx >> 10);                              // FDIM/4 = 1024 v4 per row
    if (g_tok[slot] < 0) return;
    float4 g = ((const float4*)g_hg)[idx];
    float4 u = ((const float4*)g_hu)[idx];
    g.x = g.x / (1.f + expf(-g.x)) * u.x;
    g.y = g.y / (1.f + expf(-g.y)) * u.y;
    g.z = g.z / (1.f + expf(-g.z)) * u.z;
    g.w = g.w / (1.f + expf(-g.w)) * u.w;
    ((float4*)g_hg)[idx] = g;
}

// ---------------- GEMM2 (tf32 mma): y = act @ Wo^T, K = FDIM, scaled scatter ----------------
// grid: (DDIM/128, SLOTS_PER_E/128, NEXP), block 256, dyn smem
__global__ void __launch_bounds__(256, 2) gemm2_mma(const float* __restrict__ wo)
{
    int e = blockIdx.z;
    int m0 = blockIdx.y * 128;
    int seg = (m0 >= CAP) ? 1 : 0;
    int lim = min(g_cnt[seg*NEXP + e], CAP);
    if ((m0 - seg*CAP) >= lim) return;

    const float* W = wo + (size_t)e * DDIM * FDIM;
    const float* A = g_hg + (size_t)e * SLOTS_PER_E * FDIM;
    int n0 = blockIdx.x * 128;

    extern __shared__ float sm[];
    float* sA = sm;
    float* sB = sm + STAGES*A_STAGE;

    int tid = threadIdx.x;
    int ar = tid >> 2;
    int ac = (tid & 3) << 2;
    const float* ap0 = A + (size_t)(m0 + ar) * FDIM + ac;
    const float* ap1 = A + (size_t)(m0 + ar + 64) * FDIM + ac;
    const float* bp0 = W + (size_t)(n0 + ar) * FDIM + ac;
    const float* bp1 = W + (size_t)(n0 + ar + 64) * FDIM + ac;

    const int KT = FDIM / BK;   // 256

#pragma unroll
    for (int s = 0; s < STAGES-1; s++) {
        float* dA = sA + s*A_STAGE;
        float* dB = sB + s*A_STAGE;
        int k0 = s * BK;
        cp_async16(dA + ar*ASTRIDE + ac,      ap0 + k0, 16);
        cp_async16(dA + (ar+64)*ASTRIDE + ac, ap1 + k0, 16);
        cp_async16(dB + ar*ASTRIDE + ac,      bp0 + k0, 16);
        cp_async16(dB + (ar+64)*ASTRIDE + ac, bp1 + k0, 16);
        cp_commit();
    }

    float acc[4][4][4];
#pragma unroll
    for (int a = 0; a < 4; a++)
#pragma unroll
        for (int b = 0; b < 4; b++)
#pragma unroll
            for (int c = 0; c < 4; c++) acc[a][b][c] = 0.f;

    int wid = tid >> 5, lane = tid & 31;
    int wm = wid & 1, wn = wid >> 1;
    int g = lane >> 2, tg = lane & 3;

    for (int kt = 0; kt < KT; kt++) {
        cp_wait();
        __syncthreads();
        int pf = kt + STAGES - 1;
        if (pf < KT) {
            int st = pf % STAGES;
            float* dA = sA + st*A_STAGE;
            float* dB = sB + st*A_STAGE;
            int k0 = pf * BK;
            cp_async16(dA + ar*ASTRIDE + ac,      ap0 + k0, 16);
            cp_async16(dA + (ar+64)*ASTRIDE + ac, ap1 + k0, 16);
            cp_async16(dB + ar*ASTRIDE + ac,      bp0 + k0, 16);
            cp_async16(dB + (ar+64)*ASTRIDE + ac, bp1 + k0, 16);
        }
        cp_commit();
        const float* a_s = sA + (kt % STAGES)*A_STAGE;
        const float* b_s = sB + (kt % STAGES)*A_STAGE;
#pragma unroll
        for (int kk = 0; kk < BK; kk += 8) {
            unsigned af[4][4], bf[4][2];
#pragma unroll
            for (int mt = 0; mt < 4; mt++) {
                int r = wm*64 + mt*16 + g;
                const float* p = a_s + r*ASTRIDE + kk + tg;
                af[mt][0] = f2tf(p[0]);
                af[mt][1] = f2tf(p[8*ASTRIDE]);
                af[mt][2] = f2tf(p[4]);
                af[mt][3] = f2tf(p[8*ASTRIDE + 4]);
            }
#pragma unroll
            for (int nt = 0; nt < 4; nt++) {
                int n = wn*32 + nt*8 + g;
                const float* p = b_s + n*ASTRIDE + kk + tg;
                bf[nt][0] = f2tf(p[0]);
                bf[nt][1] = f2tf(p[4]);
            }
#pragma unroll
            for (int mt = 0; mt < 4; mt++)
#pragma unroll
                for (int nt = 0; nt < 4; nt++)
                    mma_tf32(acc[mt][nt], af[mt], bf[nt]);
        }
    }

#pragma unroll
    for (int mt = 0; mt < 4; mt++) {
        int r0 = m0 + wm*64 + mt*16 + g;
        int slot0 = e*SLOTS_PER_E + r0;
        int t0 = g_tok[slot0];
        int t1 = g_tok[slot0 + 8];
        float w0 = g_wgt[slot0];
        float w1 = g_wgt[slot0 + 8];
#pragma unroll
        for (int nt = 0; nt < 4; nt++) {
            int c0 = n0 + wn*32 + nt*8 + tg*2;
            if (t0 >= 0) {
                float2 v = make_float2(acc[mt][nt][0]*w0, acc[mt][nt][1]*w0);
                *(float2*)&g_ybuf[((size_t)t0*2 + seg)*DDIM + c0] = v;
            }
            if (t1 >= 0) {
                float2 v = make_float2(acc[mt][nt][2]*w1, acc[mt][nt][3]*w1);
                *(float2*)&g_ybuf[((size_t)t1*2 + seg)*DDIM + c0] = v;
            }
        }
    }
}

// ---------------- combine: out[t] = ybuf[t,0] + ybuf[t,1] (validity-masked) ----------------
__global__ void __launch_bounds__(256) combine_kernel(float* __restrict__ out)
{
    int t = blockIdx.x;
    bool v0 = g_rank[t] < CAP;
    bool v1 = g_rank[N_TOK + t] < CAP;
    const float4* y0 = (const float4*)(g_ybuf + (size_t)t * 2 * DDIM);
    const float4* y1 = y0 + DDIM/4;
    float4 a = v0 ? y0[threadIdx.x] : make_float4(0.f,0.f,0.f,0.f);
    float4 b = v1 ? y1[threadIdx.x] : make_float4(0.f,0.f,0.f,0.f);
    float4 r = make_float4(a.x+b.x, a.y+b.y, a.z+b.z, a.w+b.w);
    ((float4*)(out + (size_t)t * DDIM))[threadIdx.x] = r;
}

// ---------------- aux loss: deterministic tree reduction ----------------
__global__ void __launch_bounds__(1024) aux_kernel(float* __restrict__ out_aux)
{
    __shared__ float sb[1024];
    __shared__ float res[9];
    int tid = threadIdx.x;
    float pacc[NEXP];
#pragma unroll
    for (int e = 0; e < NEXP; e++) pacc[e] = 0.f;
    float zacc = 0.f;
    for (int i = 0; i < N_TOK/1024; i++) {
        int t = tid * (N_TOK/1024) + i;
        const float* pr = g_probs + (size_t)t * NEXP;
#pragma unroll
        for (int e = 0; e < NEXP; e++) pacc[e] += pr[e];
        float l = g_lse[t];
        zacc += l * l;
    }
    for (int e = 0; e < NEXP; e++) {
        sb[tid] = pacc[e];
        __syncthreads();
        for (int s = 512; s > 0; s >>= 1) {
            if (tid < s) sb[tid] += sb[tid + s];
            __syncthreads();
        }
        if (tid == 0) res[e] = sb[0];
        __syncthreads();
    }
    sb[tid] = zacc;
    __syncthreads();
    for (int s = 512; s > 0; s >>= 1) {
        if (tid < s) sb[tid] += sb[tid + s];
        __syncthreads();
    }
    if (tid == 0) res[8] = sb[0];
    __syncthreads();
    if (tid == 0) {
        float lb = 0.f;
#pragma unroll
        for (int e = 0; e < NEXP; e++) {
            float density = (float)(g_cnt[e] + g_cnt[NEXP + e]) / (float)(N_TOK * 2);
            float mean_p = res[e] / (float)N_TOK;
            lb += density * mean_p;
        }
        lb *= 0.01f * (float)NEXP;
        float z = 0.001f * (res[8] / (float)N_TOK);
        out_aux[0] = lb + z;
    }
}

// ---------------- launch ----------------
extern "C" void kernel_launch(void* const* d_in, const int* in_sizes, int n_in,
                              void* d_out, int out_size)
{
    const float* x       = (const float*)d_in[0];
    const float* gate_w  = (const float*)d_in[1];
    const float* wi_gate = (const float*)d_in[2];
    const float* wi_up   = (const float*)d_in[3];
    const float* wo      = (const float*)d_in[4];
    float* out = (float*)d_out;

    static bool s_attr = false;
    if (!s_attr) {
        cudaFuncSetAttribute(gemm1_mma, cudaFuncAttributeMaxDynamicSharedMemorySize, SMEM_BYTES);
        cudaFuncSetAttribute(gemm2_mma, cudaFuncAttributeMaxDynamicSharedMemorySize, SMEM_BYTES);
        s_attr = true;
    }

    clear_tok_kernel<<<(TOT_SLOTS + 255)/256, 256>>>();
    router_kernel<<<N_TOK, 256>>>(x, gate_w);
    rank_kernel<<<16, 256>>>();
    build_kernel<<<N_TOK/256, 256>>>();

    gemm1_mma<<<dim3(FDIM/128, SLOTS_PER_E/128, NEXP*2), 256, SMEM_BYTES>>>(x, wi_gate, wi_up);

    size_t n_v4 = (size_t)NEXP * SLOTS_PER_E * FDIM / 4;
    act_kernel<<<(unsigned)(n_v4 / 256), 256>>>();

    gemm2_mma<<<dim3(DDIM/128, SLOTS_PER_E/128, NEXP), 256, SMEM_BYTES>>>(wo);

    combine_kernel<<<N_TOK, 256>>>(out);

    if (out_size > N_TOK * DDIM) {
        aux_kernel<<<1, 1024>>>(out + (size_t)N_TOK * DDIM);
    }
}

// round 3
// speedup vs baseline: 2.7597x; 1.0316x over previous
#include <cuda_runtime.h>
#include <cuda_bf16.h>
#include <math.h>

// Problem constants
#define N_TOK   8192
#define DDIM    1024
#define FDIM    4096
#define NEXP    8
#define CAP     1280          // int(8192/8 * 1.25)
#define SLOTS_PER_E (2*CAP)   // 2560 (k=0 segment [0,1280), k=1 segment [1280,2560))
#define TOT_SLOTS (NEXP*SLOTS_PER_E)

// GEMM tiling
#define STAGES  4
#define BK      16
#define ASTRIDE 20                 // floats per smem row (16 + 4 pad)
#define A_STAGE (128*ASTRIDE)      // floats per stage per operand
#define SMEM_BYTES (STAGES*2*A_STAGE*4)   // 81920

// ---------------- scratch (static __device__, no runtime allocs) ----------------
__device__ float g_hg[(size_t)NEXP*SLOTS_PER_E*FDIM];   // fused activation output
__device__ float g_ybuf[(size_t)N_TOK*2*DDIM];          // per-(token,k) expert output (scaled)
__device__ int   g_tok[TOT_SLOTS];                      // slot -> token id (-1 = empty)
__device__ float g_wgt[TOT_SLOTS];                      // slot -> combine weight
__device__ int   g_eids[N_TOK*2];
__device__ float g_ew[N_TOK*2];
__device__ float g_probs[N_TOK*NEXP];
__device__ float g_lse[N_TOK];
__device__ int   g_rank[2*N_TOK];                       // exclusive rank within (k, expert) stream
__device__ int   g_cnt[2*NEXP];                         // raw counts per (k, expert)

// ---------------- helpers ----------------
__device__ __forceinline__ void cp_async16(float* dst, const float* src, int bytes)
{
    unsigned s = (unsigned)__cvta_generic_to_shared(dst);
    asm volatile("cp.async.ca.shared.global [%0], [%1], 16, %2;\n"
                 :: "r"(s), "l"(src), "r"(bytes));
}
__device__ __forceinline__ void cp_commit() { asm volatile("cp.async.commit_group;\n"); }
__device__ __forceinline__ void cp_wait()   { asm volatile("cp.async.wait_group %0;\n" :: "n"(STAGES-2)); }

__device__ __forceinline__ unsigned f2tf(float f)
{
    unsigned u;
    asm("cvt.rna.tf32.f32 %0, %1;\n" : "=r"(u) : "f"(f));
    return u;
}

__device__ __forceinline__ void mma_tf32(float* c, const unsigned* a, const unsigned* b)
{
    asm volatile(
        "mma.sync.aligned.m16n8k8.row.col.f32.tf32.tf32.f32 "
        "{%0,%1,%2,%3}, {%4,%5,%6,%7}, {%8,%9}, {%0,%1,%2,%3};\n"
        : "+f"(c[0]), "+f"(c[1]), "+f"(c[2]), "+f"(c[3])
        : "r"(a[0]), "r"(a[1]), "r"(a[2]), "r"(a[3]), "r"(b[0]), "r"(b[1]));
}

__device__ __forceinline__ float silu_mul(float g, float u)
{
    return g / (1.f + expf(-g)) * u;
}

// ---------------- router: logits, softmax, top-2, weights ----------------
__global__ void __launch_bounds__(256) router_kernel(const float* __restrict__ x,
                                                     const float* __restrict__ gw)
{
    int t = blockIdx.x;
    const float* xr = x + (size_t)t * DDIM;
    __shared__ float sred[NEXP][256];
    float acc[NEXP];
#pragma unroll
    for (int e = 0; e < NEXP; e++) acc[e] = 0.f;
    for (int d = threadIdx.x; d < DDIM; d += 256) {
        float xv = xr[d];
#pragma unroll
        for (int e = 0; e < NEXP; e++) acc[e] += xv * gw[e*DDIM + d];
    }
#pragma unroll
    for (int e = 0; e < NEXP; e++) sred[e][threadIdx.x] = acc[e];
    __syncthreads();
    for (int s = 128; s > 0; s >>= 1) {
        if (threadIdx.x < s) {
#pragma unroll
            for (int e = 0; e < NEXP; e++) sred[e][threadIdx.x] += sred[e][threadIdx.x + s];
        }
        __syncthreads();
    }
    if (threadIdx.x == 0) {
        float lg[NEXP];
#pragma unroll
        for (int e = 0; e < NEXP; e++) lg[e] = sred[e][0];
        float mx = lg[0];
#pragma unroll
        for (int e = 1; e < NEXP; e++) mx = fmaxf(mx, lg[e]);
        float se = 0.f, p[NEXP];
#pragma unroll
        for (int e = 0; e < NEXP; e++) { p[e] = expf(lg[e] - mx); se += p[e]; }
        float inv = 1.f / se;
#pragma unroll
        for (int e = 0; e < NEXP; e++) { p[e] *= inv; g_probs[t*NEXP + e] = p[e]; }
        g_lse[t] = mx + logf(se);
        int i0 = 0;
#pragma unroll
        for (int e = 1; e < NEXP; e++) if (p[e] > p[i0]) i0 = e;
        int i1 = -1;
#pragma unroll
        for (int e = 0; e < NEXP; e++) {
            if (e == i0) continue;
            if (i1 < 0 || p[e] > p[i1]) i1 = e;
        }
        float s2 = p[i0] + p[i1];
        g_eids[t*2 + 0] = i0; g_eids[t*2 + 1] = i1;
        g_ew[t*2 + 0] = p[i0] / s2; g_ew[t*2 + 1] = p[i1] / s2;
    }
}

// ---------------- rank: exclusive prefix count per (k, expert) in token order ----------------
__global__ void __launch_bounds__(256) rank_kernel()
{
    int k = blockIdx.x >> 3;
    int e = blockIdx.x & 7;
    __shared__ int warp_sums[8];
    __shared__ int s_base;
    if (threadIdx.x == 0) s_base = 0;
    __syncthreads();
    int lane = threadIdx.x & 31, wid = threadIdx.x >> 5;
    for (int c = 0; c < N_TOK; c += 256) {
        int t = c + threadIdx.x;
        int flag = (g_eids[t*2 + k] == e) ? 1 : 0;
        unsigned m = __ballot_sync(0xffffffffu, flag);
        int pre = __popc(m & ((1u << lane) - 1u));
        if (lane == 31) warp_sums[wid] = pre + flag;
        __syncthreads();
        int wbase = 0;
        for (int w = 0; w < wid; w++) wbase += warp_sums[w];
        if (flag) g_rank[k*N_TOK + t] = s_base + wbase + pre;
        __syncthreads();
        if (threadIdx.x == 0) {
            int tot = 0;
            for (int w = 0; w < 8; w++) tot += warp_sums[w];
            s_base += tot;
        }
        __syncthreads();
    }
    if (threadIdx.x == 0) g_cnt[k*NEXP + e] = s_base;
}

// ---------------- clear token slots ----------------
__global__ void clear_tok_kernel()
{
    int i = blockIdx.x * 256 + threadIdx.x;
    if (i < TOT_SLOTS) { g_tok[i] = -1; g_wgt[i] = 0.f; }
}

// ---------------- build compact per-expert lists ----------------
__global__ void build_kernel()
{
    int t = blockIdx.x * 256 + threadIdx.x;
    if (t >= N_TOK) return;
#pragma unroll
    for (int k = 0; k < 2; k++) {
        int e = g_eids[t*2 + k];
        int r = g_rank[k*N_TOK + t];
        if (r < CAP) {
            int slot = e*SLOTS_PER_E + k*CAP + r;
            g_tok[slot] = t;
            g_wgt[slot] = g_ew[t*2 + k];
        }
    }
}

// ---------------- fused GEMM1: act = silu(X@Wg^T) * (X@Wu^T), K = DDIM ----------------
// grid: (FDIM/64, SLOTS_PER_E/128, NEXP), block 256, dyn smem
// CTA computes a 128x64 tile of BOTH gate and up, fuses SiLU*up, writes act only.
__global__ void __launch_bounds__(256, 2) gemm1_fused(const float* __restrict__ x,
                                                      const float* __restrict__ wi_gate,
                                                      const float* __restrict__ wi_up)
{
    int e = blockIdx.z;
    int m0 = blockIdx.y * 128;
    int seg = (m0 >= CAP) ? 1 : 0;
    int lim = min(g_cnt[seg*NEXP + e], CAP);
    if ((m0 - seg*CAP) >= lim) return;

    const float* Wg = wi_gate + (size_t)e * FDIM * DDIM;
    const float* Wu = wi_up   + (size_t)e * FDIM * DDIM;
    float* C = g_hg + (size_t)e * SLOTS_PER_E * FDIM;
    int n0 = blockIdx.x * 64;

    extern __shared__ float sm[];
    float* sA = sm;                      // 128 rows of A per stage
    float* sB = sm + STAGES*A_STAGE;     // rows [0,64): gate, [64,128): up

    int tid = threadIdx.x;
    int ar = tid >> 2;          // 0..63
    int ac = (tid & 3) << 2;    // 0,4,8,12
    int slotbase = e*SLOTS_PER_E + m0;
    int tok0 = g_tok[slotbase + ar];
    int tok1 = g_tok[slotbase + ar + 64];
    const float* ap0 = x + (size_t)max(tok0, 0) * DDIM + ac;
    const float* ap1 = x + (size_t)max(tok1, 0) * DDIM + ac;
    int sz0 = (tok0 >= 0) ? 16 : 0;
    int sz1 = (tok1 >= 0) ? 16 : 0;
    const float* bgp = Wg + (size_t)(n0 + ar) * DDIM + ac;
    const float* bup = Wu + (size_t)(n0 + ar) * DDIM + ac;

    const int KT = DDIM / BK;   // 64

#pragma unroll
    for (int s = 0; s < STAGES-1; s++) {
        float* dA = sA + s*A_STAGE;
        float* dB = sB + s*A_STAGE;
        int k0 = s * BK;
        cp_async16(dA + ar*ASTRIDE + ac,        ap0 + k0, sz0);
        cp_async16(dA + (ar+64)*ASTRIDE + ac,   ap1 + k0, sz1);
        cp_async16(dB + ar*ASTRIDE + ac,        bgp + k0, 16);
        cp_async16(dB + (ar+64)*ASTRIDE + ac,   bup + k0, 16);
        cp_commit();
    }

    float accg[2][4][4], accu[2][4][4];
#pragma unroll
    for (int a = 0; a < 2; a++)
#pragma unroll
        for (int b = 0; b < 4; b++)
#pragma unroll
            for (int c = 0; c < 4; c++) { accg[a][b][c] = 0.f; accu[a][b][c] = 0.f; }

    int wid = tid >> 5, lane = tid & 31;
    int wm = wid & 3, wn = wid >> 2;      // 4 m-warps x 2 n-warps over 128x64
    int g = lane >> 2, tg = lane & 3;

    for (int kt = 0; kt < KT; kt++) {
        cp_wait();
        __syncthreads();
        int pf = kt + STAGES - 1;
        if (pf < KT) {
            int st = pf % STAGES;
            float* dA = sA + st*A_STAGE;
            float* dB = sB + st*A_STAGE;
            int k0 = pf * BK;
            cp_async16(dA + ar*ASTRIDE + ac,      ap0 + k0, sz0);
            cp_async16(dA + (ar+64)*ASTRIDE + ac, ap1 + k0, sz1);
            cp_async16(dB + ar*ASTRIDE + ac,      bgp + k0, 16);
            cp_async16(dB + (ar+64)*ASTRIDE + ac, bup + k0, 16);
        }
        cp_commit();
        const float* a_s = sA + (kt % STAGES)*A_STAGE;
        const float* b_s = sB + (kt % STAGES)*A_STAGE;
#pragma unroll
        for (int kk = 0; kk < BK; kk += 8) {
            unsigned af[2][4], bfg[4][2], bfu[4][2];
#pragma unroll
            for (int mt = 0; mt < 2; mt++) {
                int r = wm*32 + mt*16 + g;
                const float* p = a_s + r*ASTRIDE + kk + tg;
                af[mt][0] = f2tf(p[0]);
                af[mt][1] = f2tf(p[8*ASTRIDE]);
                af[mt][2] = f2tf(p[4]);
                af[mt][3] = f2tf(p[8*ASTRIDE + 4]);
            }
#pragma unroll
            for (int nt = 0; nt < 4; nt++) {
                int n = wn*32 + nt*8 + g;
                const float* pg = b_s + n*ASTRIDE + kk + tg;
                const float* pu = b_s + (64 + n)*ASTRIDE + kk + tg;
                bfg[nt][0] = f2tf(pg[0]); bfg[nt][1] = f2tf(pg[4]);
                bfu[nt][0] = f2tf(pu[0]); bfu[nt][1] = f2tf(pu[4]);
            }
#pragma unroll
            for (int mt = 0; mt < 2; mt++)
#pragma unroll
                for (int nt = 0; nt < 4; nt++) {
                    mma_tf32(accg[mt][nt], af[mt], bfg[nt]);
                    mma_tf32(accu[mt][nt], af[mt], bfu[nt]);
                }
        }
    }

#pragma unroll
    for (int mt = 0; mt < 2; mt++) {
        int r0 = m0 + wm*32 + mt*16 + g;
#pragma unroll
        for (int nt = 0; nt < 4; nt++) {
            int c0 = n0 + wn*32 + nt*8 + tg*2;
            float2 v0, v1;
            v0.x = silu_mul(accg[mt][nt][0], accu[mt][nt][0]);
            v0.y = silu_mul(accg[mt][nt][1], accu[mt][nt][1]);
            v1.x = silu_mul(accg[mt][nt][2], accu[mt][nt][2]);
            v1.y = silu_mul(accg[mt][nt][3], accu[mt][nt][3]);
            *(float2*)&C[(size_t)r0*FDIM + c0]     = v0;
            *(float2*)&C[(size_t)(r0+8)*FDIM + c0] = v1;
        }
    }
}

// ---------------- GEMM2 (tf32 mma): y = act @ Wo^T, K = FDIM, scaled scatter ----------------
// grid: (DDIM/128, SLOTS_PER_E/128, NEXP), block 256, dyn smem
__global__ void __launch_bounds__(256, 2) gemm2_mma(const float* __restrict__ wo)
{
    int e = blockIdx.z;
    int m0 = blockIdx.y * 128;
    int seg = (m0 >= CAP) ? 1 : 0;
    int lim = min(g_cnt[seg*NEXP + e], CAP);
    if ((m0 - seg*CAP) >= lim) return;

    const float* W = wo + (size_t)e * DDIM * FDIM;
    const float* A = g_hg + (size_t)e * SLOTS_PER_E * FDIM;
    int n0 = blockIdx.x * 128;

    extern __shared__ float sm[];
    float* sA = sm;
    float* sB = sm + STAGES*A_STAGE;

    int tid = threadIdx.x;
    int ar = tid >> 2;
    int ac = (tid & 3) << 2;
    const float* ap0 = A + (size_t)(m0 + ar) * FDIM + ac;
    const float* ap1 = A + (size_t)(m0 + ar + 64) * FDIM + ac;
    const float* bp0 = W + (size_t)(n0 + ar) * FDIM + ac;
    const float* bp1 = W + (size_t)(n0 + ar + 64) * FDIM + ac;

    const int KT = FDIM / BK;   // 256

#pragma unroll
    for (int s = 0; s < STAGES-1; s++) {
        float* dA = sA + s*A_STAGE;
        float* dB = sB + s*A_STAGE;
        int k0 = s * BK;
        cp_async16(dA + ar*ASTRIDE + ac,      ap0 + k0, 16);
        cp_async16(dA + (ar+64)*ASTRIDE + ac, ap1 + k0, 16);
        cp_async16(dB + ar*ASTRIDE + ac,      bp0 + k0, 16);
        cp_async16(dB + (ar+64)*ASTRIDE + ac, bp1 + k0, 16);
        cp_commit();
    }

    float acc[4][4][4];
#pragma unroll
    for (int a = 0; a < 4; a++)
#pragma unroll
        for (int b = 0; b < 4; b++)
#pragma unroll
            for (int c = 0; c < 4; c++) acc[a][b][c] = 0.f;

    int wid = tid >> 5, lane = tid & 31;
    int wm = wid & 1, wn = wid >> 1;
    int g = lane >> 2, tg = lane & 3;

    for (int kt = 0; kt < KT; kt++) {
        cp_wait();
        __syncthreads();
        int pf = kt + STAGES - 1;
        if (pf < KT) {
            int st = pf % STAGES;
            float* dA = sA + st*A_STAGE;
            float* dB = sB + st*A_STAGE;
            int k0 = pf * BK;
            cp_async16(dA + ar*ASTRIDE + ac,      ap0 + k0, 16);
            cp_async16(dA + (ar+64)*ASTRIDE + ac, ap1 + k0, 16);
            cp_async16(dB + ar*ASTRIDE + ac,      bp0 + k0, 16);
            cp_async16(dB + (ar+64)*ASTRIDE + ac, bp1 + k0, 16);
        }
        cp_commit();
        const float* a_s = sA + (kt % STAGES)*A_STAGE;
        const float* b_s = sB + (kt % STAGES)*A_STAGE;
#pragma unroll
        for (int kk = 0; kk < BK; kk += 8) {
            unsigned af[4][4], bf[4][2];
#pragma unroll
            for (int mt = 0; mt < 4; mt++) {
                int r = wm*64 + mt*16 + g;
                const float* p = a_s + r*ASTRIDE + kk + tg;
                af[mt][0] = f2tf(p[0]);
                af[mt][1] = f2tf(p[8*ASTRIDE]);
                af[mt][2] = f2tf(p[4]);
                af[mt][3] = f2tf(p[8*ASTRIDE + 4]);
            }
#pragma unroll
            for (int nt = 0; nt < 4; nt++) {
                int n = wn*32 + nt*8 + g;
                const float* p = b_s + n*ASTRIDE + kk + tg;
                bf[nt][0] = f2tf(p[0]);
                bf[nt][1] = f2tf(p[4]);
            }
#pragma unroll
            for (int mt = 0; mt < 4; mt++)
#pragma unroll
                for (int nt = 0; nt < 4; nt++)
                    mma_tf32(acc[mt][nt], af[mt], bf[nt]);
        }
    }

#pragma unroll
    for (int mt = 0; mt < 4; mt++) {
        int r0 = m0 + wm*64 + mt*16 + g;
        int slot0 = e*SLOTS_PER_E + r0;
        int t0 = g_tok[slot0];
        int t1 = g_tok[slot0 + 8];
        float w0 = g_wgt[slot0];
        float w1 = g_wgt[slot0 + 8];
#pragma unroll
        for (int nt = 0; nt < 4; nt++) {
            int c0 = n0 + wn*32 + nt*8 + tg*2;
            if (t0 >= 0) {
                float2 v = make_float2(acc[mt][nt][0]*w0, acc[mt][nt][1]*w0);
                *(float2*)&g_ybuf[((size_t)t0*2 + seg)*DDIM + c0] = v;
            }
            if (t1 >= 0) {
                float2 v = make_float2(acc[mt][nt][2]*w1, acc[mt][nt][3]*w1);
                *(float2*)&g_ybuf[((size_t)t1*2 + seg)*DDIM + c0] = v;
            }
        }
    }
}

// ---------------- combine: out[t] = ybuf[t,0] + ybuf[t,1] (validity-masked) ----------------
__global__ void __launch_bounds__(256) combine_kernel(float* __restrict__ out)
{
    int t = blockIdx.x;
    bool v0 = g_rank[t] < CAP;
    bool v1 = g_rank[N_TOK + t] < CAP;
    const float4* y0 = (const float4*)(g_ybuf + (size_t)t * 2 * DDIM);
    const float4* y1 = y0 + DDIM/4;
    float4 a = v0 ? y0[threadIdx.x] : make_float4(0.f,0.f,0.f,0.f);
    float4 b = v1 ? y1[threadIdx.x] : make_float4(0.f,0.f,0.f,0.f);
    float4 r = make_float4(a.x+b.x, a.y+b.y, a.z+b.z, a.w+b.w);
    ((float4*)(out + (size_t)t * DDIM))[threadIdx.x] = r;
}

// ---------------- aux loss: deterministic tree reduction ----------------
__global__ void __launch_bounds__(1024) aux_kernel(float* __restrict__ out_aux)
{
    __shared__ float sb[1024];
    __shared__ float res[9];
    int tid = threadIdx.x;
    float pacc[NEXP];
#pragma unroll
    for (int e = 0; e < NEXP; e++) pacc[e] = 0.f;
    float zacc = 0.f;
    for (int i = 0; i < N_TOK/1024; i++) {
        int t = tid * (N_TOK/1024) + i;
        const float* pr = g_probs + (size_t)t * NEXP;
#pragma unroll
        for (int e = 0; e < NEXP; e++) pacc[e] += pr[e];
        float l = g_lse[t];
        zacc += l * l;
    }
    for (int e = 0; e < NEXP; e++) {
        sb[tid] = pacc[e];
        __syncthreads();
        for (int s = 512; s > 0; s >>= 1) {
            if (tid < s) sb[tid] += sb[tid + s];
            __syncthreads();
        }
        if (tid == 0) res[e] = sb[0];
        __syncthreads();
    }
    sb[tid] = zacc;
    __syncthreads();
    for (int s = 512; s > 0; s >>= 1) {
        if (tid < s) sb[tid] += sb[tid + s];
        __syncthreads();
    }
    if (tid == 0) res[8] = sb[0];
    __syncthreads();
    if (tid == 0) {
        float lb = 0.f;
#pragma unroll
        for (int e = 0; e < NEXP; e++) {
            float density = (float)(g_cnt[e] + g_cnt[NEXP + e]) / (float)(N_TOK * 2);
            float mean_p = res[e] / (float)N_TOK;
            lb += density * mean_p;
        }
        lb *= 0.01f * (float)NEXP;
        float z = 0.001f * (res[8] / (float)N_TOK);
        out_aux[0] = lb + z;
    }
}

// ---------------- launch ----------------
extern "C" void kernel_launch(void* const* d_in, const int* in_sizes, int n_in,
                              void* d_out, int out_size)
{
    const float* x       = (const float*)d_in[0];
    const float* gate_w  = (const float*)d_in[1];
    const float* wi_gate = (const float*)d_in[2];
    const float* wi_up   = (const float*)d_in[3];
    const float* wo      = (const float*)d_in[4];
    float* out = (float*)d_out;

    static bool s_attr = false;
    if (!s_attr) {
        cudaFuncSetAttribute(gemm1_fused, cudaFuncAttributeMaxDynamicSharedMemorySize, SMEM_BYTES);
        cudaFuncSetAttribute(gemm2_mma,   cudaFuncAttributeMaxDynamicSharedMemorySize, SMEM_BYTES);
        s_attr = true;
    }

    clear_tok_kernel<<<(TOT_SLOTS + 255)/256, 256>>>();
    router_kernel<<<N_TOK, 256>>>(x, gate_w);
    rank_kernel<<<16, 256>>>();
    build_kernel<<<N_TOK/256, 256>>>();

    gemm1_fused<<<dim3(FDIM/64, SLOTS_PER_E/128, NEXP), 256, SMEM_BYTES>>>(x, wi_gate, wi_up);

    gemm2_mma<<<dim3(DDIM/128, SLOTS_PER_E/128, NEXP), 256, SMEM_BYTES>>>(wo);

    combine_kernel<<<N_TOK, 256>>>(out);

    if (out_size > N_TOK * DDIM) {
        aux_kernel<<<1, 1024>>>(out + (size_t)N_TOK * DDIM);
    }
}

// round 5
// speedup vs baseline: 4.3309x; 1.5693x over previous
#include <cuda_runtime.h>
#include <cuda_fp16.h>
#include <cstdint>
#include <math.h>

// Problem constants
#define N_TOK   8192
#define DDIM    1024
#define FDIM    4096
#define NEXP    8
#define CAP     1280          // int(8192/8 * 1.25)
#define SLOTS_PER_E (2*CAP)   // 2560
#define TOT_SLOTS (NEXP*SLOTS_PER_E)

// fp16 GEMM tiling
#define STAGES  4
#define BKH     32                  // halves per K-chunk
#define HSTRIDE 40                  // halves per smem row (32 + 8 pad -> 80B, 16B-multiple)
#define H_STAGE (128*HSTRIDE)       // halves per operand per stage
#define SMEM_BYTES (STAGES*2*H_STAGE*2)   // 81920

// ---------------- scratch (static __device__, no runtime allocs) ----------------
__device__ __half g_xh[(size_t)N_TOK*DDIM];             // fp16 x
__device__ __half g_wgh[(size_t)NEXP*FDIM*DDIM];        // fp16 wi_gate
__device__ __half g_wuh[(size_t)NEXP*FDIM*DDIM];        // fp16 wi_up
__device__ __half g_woh[(size_t)NEXP*DDIM*FDIM];        // fp16 wo
__device__ __half g_hh[(size_t)NEXP*SLOTS_PER_E*FDIM];  // fp16 fused activation
__device__ float g_ybuf[(size_t)N_TOK*2*DDIM];          // per-(token,k) expert output (scaled)
__device__ int   g_tok[TOT_SLOTS];
__device__ float g_wgt[TOT_SLOTS];
__device__ int   g_eids[N_TOK*2];
__device__ float g_ew[N_TOK*2];
__device__ float g_probs[N_TOK*NEXP];
__device__ float g_lse[N_TOK];
__device__ int   g_rank[2*N_TOK];
__device__ int   g_cnt[2*NEXP];

// ---------------- helpers ----------------
__device__ __forceinline__ void cp_async16(void* dst, const void* src, int bytes)
{
    unsigned s = (unsigned)__cvta_generic_to_shared(dst);
    asm volatile("cp.async.ca.shared.global [%0], [%1], 16, %2;\n"
                 :: "r"(s), "l"(src), "r"(bytes));
}
__device__ __forceinline__ void cp_commit() { asm volatile("cp.async.commit_group;\n"); }
__device__ __forceinline__ void cp_wait()   { asm volatile("cp.async.wait_group %0;\n" :: "n"(STAGES-2)); }

__device__ __forceinline__ void mma_f16(float* c, const unsigned* a, const unsigned* b)
{
    asm volatile(
        "mma.sync.aligned.m16n8k16.row.col.f32.f16.f16.f32 "
        "{%0,%1,%2,%3}, {%4,%5,%6,%7}, {%8,%9}, {%0,%1,%2,%3};\n"
        : "+f"(c[0]), "+f"(c[1]), "+f"(c[2]), "+f"(c[3])
        : "r"(a[0]), "r"(a[1]), "r"(a[2]), "r"(a[3]), "r"(b[0]), "r"(b[1]));
}

__device__ __forceinline__ float silu_mul(float g, float u)
{
    return g / (1.f + expf(-g)) * u;
}

// ---------------- fp32 -> fp16 convert ----------------
__global__ void __launch_bounds__(256) h_convert(const float2* __restrict__ src,
                                                 int which, int n2)
{
    __half2* dst = (which == 0) ? (__half2*)g_xh
                 : (which == 1) ? (__half2*)g_wgh
                 : (which == 2) ? (__half2*)g_wuh
                 :                (__half2*)g_woh;
    int stride = gridDim.x * blockDim.x;
    for (int i = blockIdx.x*blockDim.x + threadIdx.x; i < n2; i += stride) {
        dst[i] = __float22half2_rn(src[i]);
    }
}

// ---------------- router: logits, softmax, top-2, weights ----------------
__global__ void __launch_bounds__(256) router_kernel(const float* __restrict__ x,
                                                     const float* __restrict__ gw)
{
    int t = blockIdx.x;
    const float* xr = x + (size_t)t * DDIM;
    __shared__ float sred[NEXP][256];
    float acc[NEXP];
#pragma unroll
    for (int e = 0; e < NEXP; e++) acc[e] = 0.f;
    for (int d = threadIdx.x; d < DDIM; d += 256) {
        float xv = xr[d];
#pragma unroll
        for (int e = 0; e < NEXP; e++) acc[e] += xv * gw[e*DDIM + d];
    }
#pragma unroll
    for (int e = 0; e < NEXP; e++) sred[e][threadIdx.x] = acc[e];
    __syncthreads();
    for (int s = 128; s > 0; s >>= 1) {
        if (threadIdx.x < s) {
#pragma unroll
            for (int e = 0; e < NEXP; e++) sred[e][threadIdx.x] += sred[e][threadIdx.x + s];
        }
        __syncthreads();
    }
    if (threadIdx.x == 0) {
        float lg[NEXP];
#pragma unroll
        for (int e = 0; e < NEXP; e++) lg[e] = sred[e][0];
        float mx = lg[0];
#pragma unroll
        for (int e = 1; e < NEXP; e++) mx = fmaxf(mx, lg[e]);
        float se = 0.f, p[NEXP];
#pragma unroll
        for (int e = 0; e < NEXP; e++) { p[e] = expf(lg[e] - mx); se += p[e]; }
        float inv = 1.f / se;
#pragma unroll
        for (int e = 0; e < NEXP; e++) { p[e] *= inv; g_probs[t*NEXP + e] = p[e]; }
        g_lse[t] = mx + logf(se);
        int i0 = 0;
#pragma unroll
        for (int e = 1; e < NEXP; e++) if (p[e] > p[i0]) i0 = e;
        int i1 = -1;
#pragma unroll
        for (int e = 0; e < NEXP; e++) {
            if (e == i0) continue;
            if (i1 < 0 || p[e] > p[i1]) i1 = e;
        }
        float s2 = p[i0] + p[i1];
        g_eids[t*2 + 0] = i0; g_eids[t*2 + 1] = i1;
        g_ew[t*2 + 0] = p[i0] / s2; g_ew[t*2 + 1] = p[i1] / s2;
    }
}

// ---------------- rank: exclusive prefix count per (k, expert) in token order ----------------
__global__ void __launch_bounds__(256) rank_kernel()
{
    int k = blockIdx.x >> 3;
    int e = blockIdx.x & 7;
    __shared__ int warp_sums[8];
    __shared__ int s_base;
    if (threadIdx.x == 0) s_base = 0;
    __syncthreads();
    int lane = threadIdx.x & 31, wid = threadIdx.x >> 5;
    for (int c = 0; c < N_TOK; c += 256) {
        int t = c + threadIdx.x;
        int flag = (g_eids[t*2 + k] == e) ? 1 : 0;
        unsigned m = __ballot_sync(0xffffffffu, flag);
        int pre = __popc(m & ((1u << lane) - 1u));
        if (lane == 31) warp_sums[wid] = pre + flag;
        __syncthreads();
        int wbase = 0;
        for (int w = 0; w < wid; w++) wbase += warp_sums[w];
        if (flag) g_rank[k*N_TOK + t] = s_base + wbase + pre;
        __syncthreads();
        if (threadIdx.x == 0) {
            int tot = 0;
            for (int w = 0; w < 8; w++) tot += warp_sums[w];
            s_base += tot;
        }
        __syncthreads();
    }
    if (threadIdx.x == 0) g_cnt[k*NEXP + e] = s_base;
}

// ---------------- clear token slots ----------------
__global__ void clear_tok_kernel()
{
    int i = blockIdx.x * 256 + threadIdx.x;
    if (i < TOT_SLOTS) { g_tok[i] = -1; g_wgt[i] = 0.f; }
}

// ---------------- build compact per-expert lists ----------------
__global__ void build_kernel()
{
    int t = blockIdx.x * 256 + threadIdx.x;
    if (t >= N_TOK) return;
#pragma unroll
    for (int k = 0; k < 2; k++) {
        int e = g_eids[t*2 + k];
        int r = g_rank[k*N_TOK + t];
        if (r < CAP) {
            int slot = e*SLOTS_PER_E + k*CAP + r;
            g_tok[slot] = t;
            g_wgt[slot] = g_ew[t*2 + k];
        }
    }
}

// ---------------- fused GEMM1 (fp16 mma): act = silu(X@Wg^T) * (X@Wu^T) ----------------
// grid: (FDIM/64, SLOTS_PER_E/128, NEXP), block 256, dyn smem
// CTA: 128 rows x 64 cols of BOTH gate and up (B tile rows [0,64)=gate, [64,128)=up)
__global__ void __launch_bounds__(256, 2) gemm1_h()
{
    int e = blockIdx.z;
    int m0 = blockIdx.y * 128;
    int seg = (m0 >= CAP) ? 1 : 0;
    int lim = min(g_cnt[seg*NEXP + e], CAP);
    if ((m0 - seg*CAP) >= lim) return;

    int n0 = blockIdx.x * 64;

    extern __shared__ __half smh[];
    __half* sA = smh;
    __half* sB = smh + STAGES*H_STAGE;

    int tid = threadIdx.x;
    int ar = tid >> 1;              // 0..127
    int hc = (tid & 1) * 16;        // half offset: 0 or 16
    int tok = g_tok[e*SLOTS_PER_E + m0 + ar];
    const __half* ap = g_xh + (size_t)max(tok, 0) * DDIM + hc;
    int abytes = (tok >= 0) ? 16 : 0;
    const __half* bp = (ar < 64)
        ? (g_wgh + ((size_t)e*FDIM + n0 + ar) * DDIM + hc)
        : (g_wuh + ((size_t)e*FDIM + n0 + (ar - 64)) * DDIM + hc);

    const int KT = DDIM / BKH;      // 32

#pragma unroll
    for (int s = 0; s < STAGES-1; s++) {
        __half* dA = sA + s*H_STAGE + ar*HSTRIDE + hc;
        __half* dB = sB + s*H_STAGE + ar*HSTRIDE + hc;
        int k0 = s * BKH;
        cp_async16(dA,     ap + k0,     abytes);
        cp_async16(dA + 8, ap + k0 + 8, abytes);
        cp_async16(dB,     bp + k0,     16);
        cp_async16(dB + 8, bp + k0 + 8, 16);
        cp_commit();
    }

    float accg[2][4][4], accu[2][4][4];
#pragma unroll
    for (int a = 0; a < 2; a++)
#pragma unroll
        for (int b = 0; b < 4; b++)
#pragma unroll
            for (int c = 0; c < 4; c++) { accg[a][b][c] = 0.f; accu[a][b][c] = 0.f; }

    int wid = tid >> 5, lane = tid & 31;
    int wm = wid & 3, wn = wid >> 2;      // 4 m-warps(32 rows) x 2 n-warps(32 cols)
    int g = lane >> 2, tg = lane & 3;

    for (int kt = 0; kt < KT; kt++) {
        cp_wait();
        __syncthreads();
        int pf = kt + STAGES - 1;
        if (pf < KT) {
            int st = pf % STAGES;
            __half* dA = sA + st*H_STAGE + ar*HSTRIDE + hc;
            __half* dB = sB + st*H_STAGE + ar*HSTRIDE + hc;
            int k0 = pf * BKH;
            cp_async16(dA,     ap + k0,     abytes);
            cp_async16(dA + 8, ap + k0 + 8, abytes);
            cp_async16(dB,     bp + k0,     16);
            cp_async16(dB + 8, bp + k0 + 8, 16);
        }
        cp_commit();
        const __half* a_s = sA + (kt % STAGES)*H_STAGE;
        const __half* b_s = sB + (kt % STAGES)*H_STAGE;
#pragma unroll
        for (int kk = 0; kk < BKH; kk += 16) {
            unsigned af[2][4], bfg[4][2], bfu[4][2];
#pragma unroll
            for (int mt = 0; mt < 2; mt++) {
                int r = wm*32 + mt*16 + g;
                const __half* p = a_s + r*HSTRIDE + kk + 2*tg;
                af[mt][0] = *(const unsigned*)p;
                af[mt][1] = *(const unsigned*)(p + 8*HSTRIDE);
                af[mt][2] = *(const unsigned*)(p + 8);
                af[mt][3] = *(const unsigned*)(p + 8*HSTRIDE + 8);
            }
#pragma unroll
            for (int nt = 0; nt < 4; nt++) {
                int n = wn*32 + nt*8 + g;
                const __half* pg = b_s + n*HSTRIDE + kk + 2*tg;
                const __half* pu = b_s + (64 + n)*HSTRIDE + kk + 2*tg;
                bfg[nt][0] = *(const unsigned*)pg;
                bfg[nt][1] = *(const unsigned*)(pg + 8);
                bfu[nt][0] = *(const unsigned*)pu;
                bfu[nt][1] = *(const unsigned*)(pu + 8);
            }
#pragma unroll
            for (int mt = 0; mt < 2; mt++)
#pragma unroll
                for (int nt = 0; nt < 4; nt++) {
                    mma_f16(accg[mt][nt], af[mt], bfg[nt]);
                    mma_f16(accu[mt][nt], af[mt], bfu[nt]);
                }
        }
    }

    // epilogue: silu(g)*u -> fp16 store
#pragma unroll
    for (int mt = 0; mt < 2; mt++) {
        int r0 = m0 + wm*32 + mt*16 + g;
        __half* row0 = g_hh + ((size_t)e*SLOTS_PER_E + r0) * FDIM;
        __half* row1 = g_hh + ((size_t)e*SLOTS_PER_E + r0 + 8) * FDIM;
#pragma unroll
        for (int nt = 0; nt < 4; nt++) {
            int c0 = n0 + wn*32 + nt*8 + tg*2;
            float2 v0, v1;
            v0.x = silu_mul(accg[mt][nt][0], accu[mt][nt][0]);
            v0.y = silu_mul(accg[mt][nt][1], accu[mt][nt][1]);
            v1.x = silu_mul(accg[mt][nt][2], accu[mt][nt][2]);
            v1.y = silu_mul(accg[mt][nt][3], accu[mt][nt][3]);
            *(__half2*)(row0 + c0) = __float22half2_rn(v0);
            *(__half2*)(row1 + c0) = __float22half2_rn(v1);
        }
    }
}

// ---------------- GEMM2 (fp16 mma): y = act @ Wo^T, scaled scatter ----------------
// grid: (DDIM/128, SLOTS_PER_E/128, NEXP), block 256, dyn smem
__global__ void __launch_bounds__(256, 2) gemm2_h()
{
    int e = blockIdx.z;
    int m0 = blockIdx.y * 128;
    int seg = (m0 >= CAP) ? 1 : 0;
    int lim = min(g_cnt[seg*NEXP + e], CAP);
    if ((m0 - seg*CAP) >= lim) return;

    int n0 = blockIdx.x * 128;

    extern __shared__ __half smh[];
    __half* sA = smh;
    __half* sB = smh + STAGES*H_STAGE;

    int tid = threadIdx.x;
    int ar = tid >> 1;
    int hc = (tid & 1) * 16;
    const __half* ap = g_hh + ((size_t)e*SLOTS_PER_E + m0 + ar) * FDIM + hc;
    const __half* bp = g_woh + ((size_t)e*DDIM + n0 + ar) * FDIM + hc;

    const int KT = FDIM / BKH;      // 128

#pragma unroll
    for (int s = 0; s < STAGES-1; s++) {
        __half* dA = sA + s*H_STAGE + ar*HSTRIDE + hc;
        __half* dB = sB + s*H_STAGE + ar*HSTRIDE + hc;
        int k0 = s * BKH;
        cp_async16(dA,     ap + k0,     16);
        cp_async16(dA + 8, ap + k0 + 8, 16);
        cp_async16(dB,     bp + k0,     16);
        cp_async16(dB + 8, bp + k0 + 8, 16);
        cp_commit();
    }

    float acc[4][4][4];
#pragma unroll
    for (int a = 0; a < 4; a++)
#pragma unroll
        for (int b = 0; b < 4; b++)
#pragma unroll
            for (int c = 0; c < 4; c++) acc[a][b][c] = 0.f;

    int wid = tid >> 5, lane = tid & 31;
    int wm = wid & 1, wn = wid >> 1;      // 2 m-warps(64 rows) x 4 n-warps(32 cols)
    int g = lane >> 2, tg = lane & 3;

    for (int kt = 0; kt < KT; kt++) {
        cp_wait();
        __syncthreads();
        int pf = kt + STAGES - 1;
        if (pf < KT) {
            int st = pf % STAGES;
            __half* dA = sA + st*H_STAGE + ar*HSTRIDE + hc;
            __half* dB = sB + st*H_STAGE + ar*HSTRIDE + hc;
            int k0 = pf * BKH;
            cp_async16(dA,     ap + k0,     16);
            cp_async16(dA + 8, ap + k0 + 8, 16);
            cp_async16(dB,     bp + k0,     16);
            cp_async16(dB + 8, bp + k0 + 8, 16);
        }
        cp_commit();
        const __half* a_s = sA + (kt % STAGES)*H_STAGE;
        const __half* b_s = sB + (kt % STAGES)*H_STAGE;
#pragma unroll
        for (int kk = 0; kk < BKH; kk += 16) {
            unsigned af[4][4], bf[4][2];
#pragma unroll
            for (int mt = 0; mt < 4; mt++) {
                int r = wm*64 + mt*16 + g;
                const __half* p = a_s + r*HSTRIDE + kk + 2*tg;
                af[mt][0] = *(const unsigned*)p;
                af[mt][1] = *(const unsigned*)(p + 8*HSTRIDE);
                af[mt][2] = *(const unsigned*)(p + 8);
                af[mt][3] = *(const unsigned*)(p + 8*HSTRIDE + 8);
            }
#pragma unroll
            for (int nt = 0; nt < 4; nt++) {
                int n = wn*32 + nt*8 + g;
                const __half* p = b_s + n*HSTRIDE + kk + 2*tg;
                bf[nt][0] = *(const unsigned*)p;
                bf[nt][1] = *(const unsigned*)(p + 8);
            }
#pragma unroll
            for (int mt = 0; mt < 4; mt++)
#pragma unroll
                for (int nt = 0; nt < 4; nt++)
                    mma_f16(acc[mt][nt], af[mt], bf[nt]);
        }
    }

#pragma unroll
    for (int mt = 0; mt < 4; mt++) {
        int r0 = m0 + wm*64 + mt*16 + g;
        int slot0 = e*SLOTS_PER_E + r0;
        int t0 = g_tok[slot0];
        int t1 = g_tok[slot0 + 8];
        float w0 = g_wgt[slot0];
        float w1 = g_wgt[slot0 + 8];
#pragma unroll
        for (int nt = 0; nt < 4; nt++) {
            int c0 = n0 + wn*32 + nt*8 + tg*2;
            if (t0 >= 0) {
                float2 v = make_float2(acc[mt][nt][0]*w0, acc[mt][nt][1]*w0);
                *(float2*)&g_ybuf[((size_t)t0*2 + seg)*DDIM + c0] = v;
            }
            if (t1 >= 0) {
                float2 v = make_float2(acc[mt][nt][2]*w1, acc[mt][nt][3]*w1);
                *(float2*)&g_ybuf[((size_t)t1*2 + seg)*DDIM + c0] = v;
            }
        }
    }
}

// ---------------- combine: out[t] = ybuf[t,0] + ybuf[t,1] (validity-masked) ----------------
__global__ void __launch_bounds__(256) combine_kernel(float* __restrict__ out)
{
    int t = blockIdx.x;
    bool v0 = g_rank[t] < CAP;
    bool v1 = g_rank[N_TOK + t] < CAP;
    const float4* y0 = (const float4*)(g_ybuf + (size_t)t * 2 * DDIM);
    const float4* y1 = y0 + DDIM/4;
    float4 a = v0 ? y0[threadIdx.x] : make_float4(0.f,0.f,0.f,0.f);
    float4 b = v1 ? y1[threadIdx.x] : make_float4(0.f,0.f,0.f,0.f);
    float4 r = make_float4(a.x+b.x, a.y+b.y, a.z+b.z, a.w+b.w);
    ((float4*)(out + (size_t)t * DDIM))[threadIdx.x] = r;
}

// ---------------- aux loss: deterministic tree reduction ----------------
__global__ void __launch_bounds__(1024) aux_kernel(float* __restrict__ out_aux)
{
    __shared__ float sb[1024];
    __shared__ float res[9];
    int tid = threadIdx.x;
    float pacc[NEXP];
#pragma unroll
    for (int e = 0; e < NEXP; e++) pacc[e] = 0.f;
    float zacc = 0.f;
    for (int i = 0; i < N_TOK/1024; i++) {
        int t = tid * (N_TOK/1024) + i;
        const float* pr = g_probs + (size_t)t * NEXP;
#pragma unroll
        for (int e = 0; e < NEXP; e++) pacc[e] += pr[e];
        float l = g_lse[t];
        zacc += l * l;
    }
    for (int e = 0; e < NEXP; e++) {
        sb[tid] = pacc[e];
        __syncthreads();
        for (int s = 512; s > 0; s >>= 1) {
            if (tid < s) sb[tid] += sb[tid + s];
            __syncthreads();
        }
        if (tid == 0) res[e] = sb[0];
        __syncthreads();
    }
    sb[tid] = zacc;
    __syncthreads();
    for (int s = 512; s > 0; s >>= 1) {
        if (tid < s) sb[tid] += sb[tid + s];
        __syncthreads();
    }
    if (tid == 0) res[8] = sb[0];
    __syncthreads();
    if (tid == 0) {
        float lb = 0.f;
#pragma unroll
        for (int e = 0; e < NEXP; e++) {
            float density = (float)(g_cnt[e] + g_cnt[NEXP + e]) / (float)(N_TOK * 2);
            float mean_p = res[e] / (float)N_TOK;
            lb += density * mean_p;
        }
        lb *= 0.01f * (float)NEXP;
        float z = 0.001f * (res[8] / (float)N_TOK);
        out_aux[0] = lb + z;
    }
}

// ---------------- launch ----------------
extern "C" void kernel_launch(void* const* d_in, const int* in_sizes, int n_in,
                              void* d_out, int out_size)
{
    const float* x       = (const float*)d_in[0];
    const float* gate_w  = (const float*)d_in[1];
    const float* wi_gate = (const float*)d_in[2];
    const float* wi_up   = (const float*)d_in[3];
    const float* wo      = (const float*)d_in[4];
    float* out = (float*)d_out;

    static bool s_attr = false;
    if (!s_attr) {
        cudaFuncSetAttribute(gemm1_h, cudaFuncAttributeMaxDynamicSharedMemorySize, SMEM_BYTES);
        cudaFuncSetAttribute(gemm2_h, cudaFuncAttributeMaxDynamicSharedMemorySize, SMEM_BYTES);
        s_attr = true;
    }

    // fp32 -> fp16 conversion of GEMM operands
    h_convert<<<2048, 256>>>((const float2*)x,       0, N_TOK*DDIM/2);
    h_convert<<<2048, 256>>>((const float2*)wi_gate, 1, NEXP*FDIM*DDIM/2);
    h_convert<<<2048, 256>>>((const float2*)wi_up,   2, NEXP*FDIM*DDIM/2);
    h_convert<<<2048, 256>>>((const float2*)wo,      3, NEXP*DDIM*FDIM/2);

    clear_tok_kernel<<<(TOT_SLOTS + 255)/256, 256>>>();
    router_kernel<<<N_TOK, 256>>>(x, gate_w);
    rank_kernel<<<16, 256>>>();
    build_kernel<<<N_TOK/256, 256>>>();

    gemm1_h<<<dim3(FDIM/64, SLOTS_PER_E/128, NEXP), 256, SMEM_BYTES>>>();
    gemm2_h<<<dim3(DDIM/128, SLOTS_PER_E/128, NEXP), 256, SMEM_BYTES>>>();

    combine_kernel<<<N_TOK, 256>>>(out);

    if (out_size > N_TOK * DDIM) {
        aux_kernel<<<1, 1024>>>(out + (size_t)N_TOK * DDIM);
    }
}

// round 6
// speedup vs baseline: 5.4917x; 1.2680x over previous
#include <cuda_runtime.h>
#include <cuda_fp16.h>
#include <cstdint>
#include <math.h>

// Problem constants
#define N_TOK   8192
#define DDIM    1024
#define FDIM    4096
#define NEXP    8
#define CAP     1280          // int(8192/8 * 1.25)
#define SLOTS_PER_E (2*CAP)   // 2560
#define TOT_SLOTS (NEXP*SLOTS_PER_E)

// fp16 GEMM tiling
#define STAGES  4
#define BKH     32                  // halves per K-chunk
#define HSTRIDE 40                  // halves per smem row (32 + 8 pad -> 80B)
#define H_STAGE (128*HSTRIDE)       // halves per operand per stage
#define STAGE_B (2*H_STAGE*2)       // bytes per stage (A+B)
#define SMEM_BYTES (STAGES*STAGE_B) // 81920

// ---------------- scratch (static __device__, no runtime allocs) ----------------
__device__ __half g_xh[(size_t)N_TOK*DDIM];             // fp16 x
__device__ __half g_wgh[(size_t)NEXP*FDIM*DDIM];        // fp16 wi_gate
__device__ __half g_wuh[(size_t)NEXP*FDIM*DDIM];        // fp16 wi_up
__device__ __half g_woh[(size_t)NEXP*DDIM*FDIM];        // fp16 wo
__device__ __half g_hh[(size_t)NEXP*SLOTS_PER_E*FDIM];  // fp16 fused activation
__device__ float g_ybuf[(size_t)N_TOK*2*DDIM];          // per-(token,k) expert output (scaled)
__device__ int   g_tok[TOT_SLOTS];
__device__ float g_wgt[TOT_SLOTS];
__device__ int   g_eids[N_TOK*2];
__device__ float g_ew[N_TOK*2];
__device__ float g_probs[N_TOK*NEXP];
__device__ float g_lse[N_TOK];
__device__ int   g_rank[2*N_TOK];
__device__ int   g_cnt[2*NEXP];

// ---------------- helpers ----------------
__device__ __forceinline__ void cp_async16(void* dst, const void* src, int bytes)
{
    unsigned s = (unsigned)__cvta_generic_to_shared(dst);
    asm volatile("cp.async.ca.shared.global [%0], [%1], 16, %2;\n"
                 :: "r"(s), "l"(src), "r"(bytes));
}
__device__ __forceinline__ void cp_commit() { asm volatile("cp.async.commit_group;\n"); }
__device__ __forceinline__ void cp_wait()   { asm volatile("cp.async.wait_group %0;\n" :: "n"(STAGES-2)); }

__device__ __forceinline__ void mma_f16(float* c, const unsigned* a, const unsigned* b)
{
    asm volatile(
        "mma.sync.aligned.m16n8k16.row.col.f32.f16.f16.f32 "
        "{%0,%1,%2,%3}, {%4,%5,%6,%7}, {%8,%9}, {%0,%1,%2,%3};\n"
        : "+f"(c[0]), "+f"(c[1]), "+f"(c[2]), "+f"(c[3])
        : "r"(a[0]), "r"(a[1]), "r"(a[2]), "r"(a[3]), "r"(b[0]), "r"(b[1]));
}

__device__ __forceinline__ void ldsm_x4(unsigned* r, unsigned addr)
{
    asm volatile("ldmatrix.sync.aligned.m8n8.x4.shared.b16 {%0,%1,%2,%3}, [%4];"
                 : "=r"(r[0]), "=r"(r[1]), "=r"(r[2]), "=r"(r[3]) : "r"(addr));
}

__device__ __forceinline__ float silu_mul(float g, float u)
{
    return g / (1.f + expf(-g)) * u;
}

// ---------------- fp32 -> fp16 convert ----------------
__global__ void __launch_bounds__(256) h_convert(const float2* __restrict__ src,
                                                 int which, int n2)
{
    __half2* dst = (which == 0) ? (__half2*)g_xh
                 : (which == 1) ? (__half2*)g_wgh
                 : (which == 2) ? (__half2*)g_wuh
                 :                (__half2*)g_woh;
    int stride = gridDim.x * blockDim.x;
    for (int i = blockIdx.x*blockDim.x + threadIdx.x; i < n2; i += stride) {
        dst[i] = __float22half2_rn(src[i]);
    }
}

// ---------------- router: logits, softmax, top-2, weights ----------------
__global__ void __launch_bounds__(256) router_kernel(const float* __restrict__ x,
                                                     const float* __restrict__ gw)
{
    int t = blockIdx.x;
    const float* xr = x + (size_t)t * DDIM;
    __shared__ float sred[NEXP][256];
    float acc[NEXP];
#pragma unroll
    for (int e = 0; e < NEXP; e++) acc[e] = 0.f;
    for (int d = threadIdx.x; d < DDIM; d += 256) {
        float xv = xr[d];
#pragma unroll
        for (int e = 0; e < NEXP; e++) acc[e] += xv * gw[e*DDIM + d];
    }
#pragma unroll
    for (int e = 0; e < NEXP; e++) sred[e][threadIdx.x] = acc[e];
    __syncthreads();
    for (int s = 128; s > 0; s >>= 1) {
        if (threadIdx.x < s) {
#pragma unroll
            for (int e = 0; e < NEXP; e++) sred[e][threadIdx.x] += sred[e][threadIdx.x + s];
        }
        __syncthreads();
    }
    if (threadIdx.x == 0) {
        float lg[NEXP];
#pragma unroll
        for (int e = 0; e < NEXP; e++) lg[e] = sred[e][0];
        float mx = lg[0];
#pragma unroll
        for (int e = 1; e < NEXP; e++) mx = fmaxf(mx, lg[e]);
        float se = 0.f, p[NEXP];
#pragma unroll
        for (int e = 0; e < NEXP; e++) { p[e] = expf(lg[e] - mx); se += p[e]; }
        float inv = 1.f / se;
#pragma unroll
        for (int e = 0; e < NEXP; e++) { p[e] *= inv; g_probs[t*NEXP + e] = p[e]; }
        g_lse[t] = mx + logf(se);
        int i0 = 0;
#pragma unroll
        for (int e = 1; e < NEXP; e++) if (p[e] > p[i0]) i0 = e;
        int i1 = -1;
#pragma unroll
        for (int e = 0; e < NEXP; e++) {
            if (e == i0) continue;
            if (i1 < 0 || p[e] > p[i1]) i1 = e;
        }
        float s2 = p[i0] + p[i1];
        g_eids[t*2 + 0] = i0; g_eids[t*2 + 1] = i1;
        g_ew[t*2 + 0] = p[i0] / s2; g_ew[t*2 + 1] = p[i1] / s2;
    }
}

// ---------------- rank: exclusive prefix count per (k, expert) in token order ----------------
__global__ void __launch_bounds__(256) rank_kernel()
{
    int k = blockIdx.x >> 3;
    int e = blockIdx.x & 7;
    __shared__ int warp_sums[8];
    __shared__ int s_base;
    if (threadIdx.x == 0) s_base = 0;
    __syncthreads();
    int lane = threadIdx.x & 31, wid = threadIdx.x >> 5;
    for (int c = 0; c < N_TOK; c += 256) {
        int t = c + threadIdx.x;
        int flag = (g_eids[t*2 + k] == e) ? 1 : 0;
        unsigned m = __ballot_sync(0xffffffffu, flag);
        int pre = __popc(m & ((1u << lane) - 1u));
        if (lane == 31) warp_sums[wid] = pre + flag;
        __syncthreads();
        int wbase = 0;
        for (int w = 0; w < wid; w++) wbase += warp_sums[w];
        if (flag) g_rank[k*N_TOK + t] = s_base + wbase + pre;
        __syncthreads();
        if (threadIdx.x == 0) {
            int tot = 0;
            for (int w = 0; w < 8; w++) tot += warp_sums[w];
            s_base += tot;
        }
        __syncthreads();
    }
    if (threadIdx.x == 0) g_cnt[k*NEXP + e] = s_base;
}

// ---------------- clear token slots ----------------
__global__ void clear_tok_kernel()
{
    int i = blockIdx.x * 256 + threadIdx.x;
    if (i < TOT_SLOTS) { g_tok[i] = -1; g_wgt[i] = 0.f; }
}

// ---------------- build compact per-expert lists ----------------
__global__ void build_kernel()
{
    int t = blockIdx.x * 256 + threadIdx.x;
    if (t >= N_TOK) return;
#pragma unroll
    for (int k = 0; k < 2; k++) {
        int e = g_eids[t*2 + k];
        int r = g_rank[k*N_TOK + t];
        if (r < CAP) {
            int slot = e*SLOTS_PER_E + k*CAP + r;
            g_tok[slot] = t;
            g_wgt[slot] = g_ew[t*2 + k];
        }
    }
}

// ---------------- fused GEMM1 (fp16 mma + ldmatrix) ----------------
// grid: (FDIM/64, SLOTS_PER_E/128, NEXP), block 256, dyn smem
// CTA: 128 rows x 64 cols of BOTH gate and up (B tile rows [0,64)=gate, [64,128)=up)
__global__ void __launch_bounds__(256, 2) gemm1_h()
{
    int e = blockIdx.z;
    int m0 = blockIdx.y * 128;
    int seg = (m0 >= CAP) ? 1 : 0;
    int lim = min(g_cnt[seg*NEXP + e], CAP);
    if ((m0 - seg*CAP) >= lim) return;

    int n0 = blockIdx.x * 64;

    extern __shared__ __half smh[];
    __half* sA = smh;
    __half* sB = smh + STAGES*H_STAGE;
    unsigned sAu = (unsigned)__cvta_generic_to_shared(sA);
    unsigned sBu = (unsigned)__cvta_generic_to_shared(sB);

    int tid = threadIdx.x;
    int ar = tid >> 1;              // 0..127
    int hc = (tid & 1) * 16;
    int tok = g_tok[e*SLOTS_PER_E + m0 + ar];
    const __half* ap = g_xh + (size_t)max(tok, 0) * DDIM + hc;
    int abytes = (tok >= 0) ? 16 : 0;
    const __half* bp = (ar < 64)
        ? (g_wgh + ((size_t)e*FDIM + n0 + ar) * DDIM + hc)
        : (g_wuh + ((size_t)e*FDIM + n0 + (ar - 64)) * DDIM + hc);

    const int KT = DDIM / BKH;      // 32

#pragma unroll
    for (int s = 0; s < STAGES-1; s++) {
        __half* dA = sA + s*H_STAGE + ar*HSTRIDE + hc;
        __half* dB = sB + s*H_STAGE + ar*HSTRIDE + hc;
        int k0 = s * BKH;
        cp_async16(dA,     ap + k0,     abytes);
        cp_async16(dA + 8, ap + k0 + 8, abytes);
        cp_async16(dB,     bp + k0,     16);
        cp_async16(dB + 8, bp + k0 + 8, 16);
        cp_commit();
    }

    float accg[2][4][4], accu[2][4][4];
#pragma unroll
    for (int a = 0; a < 2; a++)
#pragma unroll
        for (int b = 0; b < 4; b++)
#pragma unroll
            for (int c = 0; c < 4; c++) { accg[a][b][c] = 0.f; accu[a][b][c] = 0.f; }

    int wid = tid >> 5, lane = tid & 31;
    int wm = wid & 3, wn = wid >> 2;      // 4 m-warps(32 rows) x 2 n-warps(32 cols)
    int g = lane >> 2, tg = lane & 3;
    int l8 = lane & 7, g1 = lane >> 3;

    // ldmatrix lane address offsets (bytes, within a stage)
    // A x4 (per mt): matrices (r0,k0),(r8,k0),(r0,k8),(r8,k8): row_off=(g1&1)*8, k_off=(g1>>1)*8
    unsigned aoff[2];
#pragma unroll
    for (int mt = 0; mt < 2; mt++)
        aoff[mt] = ((wm*32 + mt*16 + (g1 & 1)*8 + l8) * HSTRIDE + (g1 >> 1)*8) * 2;
    // B x4 (per n-pair p): matrices (n0,k0),(n0,k8),(n8,k0),(n8,k8): n_off=(g1>>1)*8, k_off=(g1&1)*8
    unsigned bgoff[2], buoff[2];
#pragma unroll
    for (int p = 0; p < 2; p++) {
        bgoff[p] = ((wn*32 + p*16 + (g1 >> 1)*8 + l8) * HSTRIDE + (g1 & 1)*8) * 2;
        buoff[p] = ((64 + wn*32 + p*16 + (g1 >> 1)*8 + l8) * HSTRIDE + (g1 & 1)*8) * 2;
    }

    for (int kt = 0; kt < KT; kt++) {
        cp_wait();
        __syncthreads();
        int pf = kt + STAGES - 1;
        if (pf < KT) {
            int st = pf % STAGES;
            __half* dA = sA + st*H_STAGE + ar*HSTRIDE + hc;
            __half* dB = sB + st*H_STAGE + ar*HSTRIDE + hc;
            int k0 = pf * BKH;
            cp_async16(dA,     ap + k0,     abytes);
            cp_async16(dA + 8, ap + k0 + 8, abytes);
            cp_async16(dB,     bp + k0,     16);
            cp_async16(dB + 8, bp + k0 + 8, 16);
        }
        cp_commit();
        unsigned stOffA = sAu + (kt % STAGES)*(H_STAGE*2);
        unsigned stOffB = sBu + (kt % STAGES)*(H_STAGE*2);
#pragma unroll
        for (int kk = 0; kk < 2; kk++) {          // kk*16 halves = kk*32 bytes
            unsigned kb = kk * 32;
            unsigned af[2][4], bg2[2][4], bu2[2][4];
#pragma unroll
            for (int mt = 0; mt < 2; mt++) ldsm_x4(af[mt], stOffA + aoff[mt] + kb);
#pragma unroll
            for (int p = 0; p < 2; p++) {
                ldsm_x4(bg2[p], stOffB + bgoff[p] + kb);
                ldsm_x4(bu2[p], stOffB + buoff[p] + kb);
            }
#pragma unroll
            for (int mt = 0; mt < 2; mt++)
#pragma unroll
                for (int p = 0; p < 2; p++) {
                    mma_f16(accg[mt][2*p+0], af[mt], &bg2[p][0]);
                    mma_f16(accg[mt][2*p+1], af[mt], &bg2[p][2]);
                    mma_f16(accu[mt][2*p+0], af[mt], &bu2[p][0]);
                    mma_f16(accu[mt][2*p+1], af[mt], &bu2[p][2]);
                }
        }
    }

    // epilogue: silu(g)*u -> fp16 store
#pragma unroll
    for (int mt = 0; mt < 2; mt++) {
        int r0 = m0 + wm*32 + mt*16 + g;
        __half* row0 = g_hh + ((size_t)e*SLOTS_PER_E + r0) * FDIM;
        __half* row1 = g_hh + ((size_t)e*SLOTS_PER_E + r0 + 8) * FDIM;
#pragma unroll
        for (int nt = 0; nt < 4; nt++) {
            int c0 = n0 + wn*32 + nt*8 + tg*2;
            float2 v0, v1;
            v0.x = silu_mul(accg[mt][nt][0], accu[mt][nt][0]);
            v0.y = silu_mul(accg[mt][nt][1], accu[mt][nt][1]);
            v1.x = silu_mul(accg[mt][nt][2], accu[mt][nt][2]);
            v1.y = silu_mul(accg[mt][nt][3], accu[mt][nt][3]);
            *(__half2*)(row0 + c0) = __float22half2_rn(v0);
            *(__half2*)(row1 + c0) = __float22half2_rn(v1);
        }
    }
}

// ---------------- GEMM2 (fp16 mma + ldmatrix): y = act @ Wo^T, scaled scatter ----------------
// grid: (DDIM/128, SLOTS_PER_E/128, NEXP), block 256, dyn smem
__global__ void __launch_bounds__(256, 2) gemm2_h()
{
    int e = blockIdx.z;
    int m0 = blockIdx.y * 128;
    int seg = (m0 >= CAP) ? 1 : 0;
    int lim = min(g_cnt[seg*NEXP + e], CAP);
    if ((m0 - seg*CAP) >= lim) return;

    int n0 = blockIdx.x * 128;

    extern __shared__ __half smh[];
    __half* sA = smh;
    __half* sB = smh + STAGES*H_STAGE;
    unsigned sAu = (unsigned)__cvta_generic_to_shared(sA);
    unsigned sBu = (unsigned)__cvta_generic_to_shared(sB);

    int tid = threadIdx.x;
    int ar = tid >> 1;
    int hc = (tid & 1) * 16;
    const __half* ap = g_hh + ((size_t)e*SLOTS_PER_E + m0 + ar) * FDIM + hc;
    const __half* bp = g_woh + ((size_t)e*DDIM + n0 + ar) * FDIM + hc;

    const int KT = FDIM / BKH;      // 128

#pragma unroll
    for (int s = 0; s < STAGES-1; s++) {
        __half* dA = sA + s*H_STAGE + ar*HSTRIDE + hc;
        __half* dB = sB + s*H_STAGE + ar*HSTRIDE + hc;
        int k0 = s * BKH;
        cp_async16(dA,     ap + k0,     16);
        cp_async16(dA + 8, ap + k0 + 8, 16);
        cp_async16(dB,     bp + k0,     16);
        cp_async16(dB + 8, bp + k0 + 8, 16);
        cp_commit();
    }

    float acc[4][4][4];
#pragma unroll
    for (int a = 0; a < 4; a++)
#pragma unroll
        for (int b = 0; b < 4; b++)
#pragma unroll
            for (int c = 0; c < 4; c++) acc[a][b][c] = 0.f;

    int wid = tid >> 5, lane = tid & 31;
    int wm = wid & 1, wn = wid >> 1;      // 2 m-warps(64 rows) x 4 n-warps(32 cols)
    int g = lane >> 2, tg = lane & 3;
    int l8 = lane & 7, g1 = lane >> 3;

    unsigned aoff[4];
#pragma unroll
    for (int mt = 0; mt < 4; mt++)
        aoff[mt] = ((wm*64 + mt*16 + (g1 & 1)*8 + l8) * HSTRIDE + (g1 >> 1)*8) * 2;
    unsigned boff[2];
#pragma unroll
    for (int p = 0; p < 2; p++)
        boff[p] = ((wn*32 + p*16 + (g1 >> 1)*8 + l8) * HSTRIDE + (g1 & 1)*8) * 2;

    for (int kt = 0; kt < KT; kt++) {
        cp_wait();
        __syncthreads();
        int pf = kt + STAGES - 1;
        if (pf < KT) {
            int st = pf % STAGES;
            __half* dA = sA + st*H_STAGE + ar*HSTRIDE + hc;
            __half* dB = sB + st*H_STAGE + ar*HSTRIDE + hc;
            int k0 = pf * BKH;
            cp_async16(dA,     ap + k0,     16);
            cp_async16(dA + 8, ap + k0 + 8, 16);
            cp_async16(dB,     bp + k0,     16);
            cp_async16(dB + 8, bp + k0 + 8, 16);
        }
        cp_commit();
        unsigned stOffA = sAu + (kt % STAGES)*(H_STAGE*2);
        unsigned stOffB = sBu + (kt % STAGES)*(H_STAGE*2);
#pragma unroll
        for (int kk = 0; kk < 2; kk++) {
            unsigned kb = kk * 32;
            unsigned af[4][4], b2[2][4];
#pragma unroll
            for (int mt = 0; mt < 4; mt++) ldsm_x4(af[mt], stOffA + aoff[mt] + kb);
#pragma unroll
            for (int p = 0; p < 2; p++) ldsm_x4(b2[p], stOffB + boff[p] + kb);
#pragma unroll
            for (int mt = 0; mt < 4; mt++)
#pragma unroll
                for (int p = 0; p < 2; p++) {
                    mma_f16(acc[mt][2*p+0], af[mt], &b2[p][0]);
                    mma_f16(acc[mt][2*p+1], af[mt], &b2[p][2]);
                }
        }
    }

#pragma unroll
    for (int mt = 0; mt < 4; mt++) {
        int r0 = m0 + wm*64 + mt*16 + g;
        int slot0 = e*SLOTS_PER_E + r0;
        int t0 = g_tok[slot0];
        int t1 = g_tok[slot0 + 8];
        float w0 = g_wgt[slot0];
        float w1 = g_wgt[slot0 + 8];
#pragma unroll
        for (int nt = 0; nt < 4; nt++) {
            int c0 = n0 + wn*32 + nt*8 + tg*2;
            if (t0 >= 0) {
                float2 v = make_float2(acc[mt][nt][0]*w0, acc[mt][nt][1]*w0);
                *(float2*)&g_ybuf[((size_t)t0*2 + seg)*DDIM + c0] = v;
            }
            if (t1 >= 0) {
                float2 v = make_float2(acc[mt][nt][2]*w1, acc[mt][nt][3]*w1);
                *(float2*)&g_ybuf[((size_t)t1*2 + seg)*DDIM + c0] = v;
            }
        }
    }
}

// ---------------- combine: out[t] = ybuf[t,0] + ybuf[t,1] (validity-masked) ----------------
__global__ void __launch_bounds__(256) combine_kernel(float* __restrict__ out)
{
    int t = blockIdx.x;
    bool v0 = g_rank[t] < CAP;
    bool v1 = g_rank[N_TOK + t] < CAP;
    const float4* y0 = (const float4*)(g_ybuf + (size_t)t * 2 * DDIM);
    const float4* y1 = y0 + DDIM/4;
    float4 a = v0 ? y0[threadIdx.x] : make_float4(0.f,0.f,0.f,0.f);
    float4 b = v1 ? y1[threadIdx.x] : make_float4(0.f,0.f,0.f,0.f);
    float4 r = make_float4(a.x+b.x, a.y+b.y, a.z+b.z, a.w+b.w);
    ((float4*)(out + (size_t)t * DDIM))[threadIdx.x] = r;
}

// ---------------- aux loss: deterministic tree reduction ----------------
__global__ void __launch_bounds__(1024) aux_kernel(float* __restrict__ out_aux)
{
    __shared__ float sb[1024];
    __shared__ float res[9];
    int tid = threadIdx.x;
    float pacc[NEXP];
#pragma unroll
    for (int e = 0; e < NEXP; e++) pacc[e] = 0.f;
    float zacc = 0.f;
    for (int i = 0; i < N_TOK/1024; i++) {
        int t = tid * (N_TOK/1024) + i;
        const float* pr = g_probs + (size_t)t * NEXP;
#pragma unroll
        for (int e = 0; e < NEXP; e++) pacc[e] += pr[e];
        float l = g_lse[t];
        zacc += l * l;
    }
    for (int e = 0; e < NEXP; e++) {
        sb[tid] = pacc[e];
        __syncthreads();
        for (int s = 512; s > 0; s >>= 1) {
            if (tid < s) sb[tid] += sb[tid + s];
            __syncthreads();
        }
        if (tid == 0) res[e] = sb[0];
        __syncthreads();
    }
    sb[tid] = zacc;
    __syncthreads();
    for (int s = 512; s > 0; s >>= 1) {
        if (tid < s) sb[tid] += sb[tid + s];
        __syncthreads();
    }
    if (tid == 0) res[8] = sb[0];
    __syncthreads();
    if (tid == 0) {
        float lb = 0.f;
#pragma unroll
        for (int e = 0; e < NEXP; e++) {
            float density = (float)(g_cnt[e] + g_cnt[NEXP + e]) / (float)(N_TOK * 2);
            float mean_p = res[e] / (float)N_TOK;
            lb += density * mean_p;
        }
        lb *= 0.01f * (float)NEXP;
        float z = 0.001f * (res[8] / (float)N_TOK);
        out_aux[0] = lb + z;
    }
}

// ---------------- launch ----------------
extern "C" void kernel_launch(void* const* d_in, const int* in_sizes, int n_in,
                              void* d_out, int out_size)
{
    const float* x       = (const float*)d_in[0];
    const float* gate_w  = (const float*)d_in[1];
    const float* wi_gate = (const float*)d_in[2];
    const float* wi_up   = (const float*)d_in[3];
    const float* wo      = (const float*)d_in[4];
    float* out = (float*)d_out;

    static bool s_attr = false;
    if (!s_attr) {
        cudaFuncSetAttribute(gemm1_h, cudaFuncAttributeMaxDynamicSharedMemorySize, SMEM_BYTES);
        cudaFuncSetAttribute(gemm2_h, cudaFuncAttributeMaxDynamicSharedMemorySize, SMEM_BYTES);
        s_attr = true;
    }

    // fp32 -> fp16 conversion of GEMM operands
    h_convert<<<2048, 256>>>((const float2*)x,       0, N_TOK*DDIM/2);
    h_convert<<<2048, 256>>>((const float2*)wi_gate, 1, NEXP*FDIM*DDIM/2);
    h_convert<<<2048, 256>>>((const float2*)wi_up,   2, NEXP*FDIM*DDIM/2);
    h_convert<<<2048, 256>>>((const float2*)wo,      3, NEXP*DDIM*FDIM/2);

    clear_tok_kernel<<<(TOT_SLOTS + 255)/256, 256>>>();
    router_kernel<<<N_TOK, 256>>>(x, gate_w);
    rank_kernel<<<16, 256>>>();
    build_kernel<<<N_TOK/256, 256>>>();

    gemm1_h<<<dim3(FDIM/64, SLOTS_PER_E/128, NEXP), 256, SMEM_BYTES>>>();
    gemm2_h<<<dim3(DDIM/128, SLOTS_PER_E/128, NEXP), 256, SMEM_BYTES>>>();

    combine_kernel<<<N_TOK, 256>>>(out);

    if (out_size > N_TOK * DDIM) {
        aux_kernel<<<1, 1024>>>(out + (size_t)N_TOK * DDIM);
    }
}

// round 7
// speedup vs baseline: 5.8638x; 1.0677x over previous
#include <cuda_runtime.h>
#include <cuda_fp16.h>
#include <cstdint>
#include <math.h>

// Problem constants
#define N_TOK   8192
#define DDIM    1024
#define FDIM    4096
#define NEXP    8
#define CAP     1280          // int(8192/8 * 1.25)
#define SLOTS_PER_E (2*CAP)   // 2560
#define TOT_SLOTS (NEXP*SLOTS_PER_E)

// fp16 GEMM tiling: 256-row M tiles
#define STAGES  4
#define BKH     32                  // halves per K-chunk
#define HSTRIDE 40                  // halves per smem row (32 + 8 pad -> 80B)
#define A_ROWS  256
#define B_ROWS  128
#define ASTG    (A_ROWS*HSTRIDE)    // halves per A stage
#define BSTG    (B_ROWS*HSTRIDE)
#define STG_H   (ASTG+BSTG)         // halves per stage
#define SMEM_BYTES (STAGES*STG_H*2) // 122880

// ---------------- scratch (static __device__, no runtime allocs) ----------------
__device__ __half g_xh[(size_t)N_TOK*DDIM];             // fp16 x
__device__ __half g_wgh[(size_t)NEXP*FDIM*DDIM];        // fp16 wi_gate
__device__ __half g_wuh[(size_t)NEXP*FDIM*DDIM];        // fp16 wi_up
__device__ __half g_woh[(size_t)NEXP*DDIM*FDIM];        // fp16 wo
__device__ __half g_hh[(size_t)NEXP*SLOTS_PER_E*FDIM];  // fp16 fused activation
__device__ float g_ybuf[(size_t)N_TOK*2*DDIM];          // per-(token,k) expert output (scaled)
__device__ int   g_tok[TOT_SLOTS];
__device__ float g_wgt[TOT_SLOTS];
__device__ int   g_eids[N_TOK*2];
__device__ float g_ew[N_TOK*2];
__device__ float g_probs[N_TOK*NEXP];
__device__ float g_lse[N_TOK];
__device__ int   g_rank[2*N_TOK];
__device__ int   g_cnt[2*NEXP];

// ---------------- helpers ----------------
__device__ __forceinline__ void cp_async16(void* dst, const void* src, int bytes)
{
    unsigned s = (unsigned)__cvta_generic_to_shared(dst);
    asm volatile("cp.async.ca.shared.global [%0], [%1], 16, %2;\n"
                 :: "r"(s), "l"(src), "r"(bytes));
}
__device__ __forceinline__ void cp_commit() { asm volatile("cp.async.commit_group;\n"); }
__device__ __forceinline__ void cp_wait()   { asm volatile("cp.async.wait_group %0;\n" :: "n"(STAGES-2)); }

__device__ __forceinline__ void mma_f16(float* c, const unsigned* a, const unsigned* b)
{
    asm volatile(
        "mma.sync.aligned.m16n8k16.row.col.f32.f16.f16.f32 "
        "{%0,%1,%2,%3}, {%4,%5,%6,%7}, {%8,%9}, {%0,%1,%2,%3};\n"
        : "+f"(c[0]), "+f"(c[1]), "+f"(c[2]), "+f"(c[3])
        : "r"(a[0]), "r"(a[1]), "r"(a[2]), "r"(a[3]), "r"(b[0]), "r"(b[1]));
}

__device__ __forceinline__ void ldsm_x4(unsigned* r, unsigned addr)
{
    asm volatile("ldmatrix.sync.aligned.m8n8.x4.shared.b16 {%0,%1,%2,%3}, [%4];"
                 : "=r"(r[0]), "=r"(r[1]), "=r"(r[2]), "=r"(r[3]) : "r"(addr));
}

__device__ __forceinline__ float silu_mul(float g, float u)
{
    return g / (1.f + expf(-g)) * u;
}

// ---------------- fused fp32 -> fp16 convert (single launch) ----------------
#define NX2 (N_TOK*DDIM/2)
#define NW2 (NEXP*FDIM*DDIM/2)
__global__ void __launch_bounds__(256) h_convert_all(const float2* __restrict__ x,
                                                     const float2* __restrict__ wg,
                                                     const float2* __restrict__ wu,
                                                     const float2* __restrict__ wo)
{
    long long total = (long long)NX2 + 3LL*NW2;
    long long stride = (long long)gridDim.x * blockDim.x;
    for (long long i = (long long)blockIdx.x*blockDim.x + threadIdx.x; i < total; i += stride) {
        if (i < NX2) {
            ((__half2*)g_xh)[i] = __float22half2_rn(x[i]);
        } else if (i < NX2 + NW2) {
            long long j = i - NX2;
            ((__half2*)g_wgh)[j] = __float22half2_rn(wg[j]);
        } else if (i < NX2 + 2LL*NW2) {
            long long j = i - NX2 - NW2;
            ((__half2*)g_wuh)[j] = __float22half2_rn(wu[j]);
        } else {
            long long j = i - NX2 - 2LL*NW2;
            ((__half2*)g_woh)[j] = __float22half2_rn(wo[j]);
        }
    }
}

// ---------------- router: logits, softmax, top-2, weights ----------------
__global__ void __launch_bounds__(256) router_kernel(const float* __restrict__ x,
                                                     const float* __restrict__ gw)
{
    int t = blockIdx.x;
    const float* xr = x + (size_t)t * DDIM;
    __shared__ float sred[NEXP][256];
    float acc[NEXP];
#pragma unroll
    for (int e = 0; e < NEXP; e++) acc[e] = 0.f;
    for (int d = threadIdx.x; d < DDIM; d += 256) {
        float xv = xr[d];
#pragma unroll
        for (int e = 0; e < NEXP; e++) acc[e] += xv * gw[e*DDIM + d];
    }
#pragma unroll
    for (int e = 0; e < NEXP; e++) sred[e][threadIdx.x] = acc[e];
    __syncthreads();
    for (int s = 128; s > 0; s >>= 1) {
        if (threadIdx.x < s) {
#pragma unroll
            for (int e = 0; e < NEXP; e++) sred[e][threadIdx.x] += sred[e][threadIdx.x + s];
        }
        __syncthreads();
    }
    if (threadIdx.x == 0) {
        float lg[NEXP];
#pragma unroll
        for (int e = 0; e < NEXP; e++) lg[e] = sred[e][0];
        float mx = lg[0];
#pragma unroll
        for (int e = 1; e < NEXP; e++) mx = fmaxf(mx, lg[e]);
        float se = 0.f, p[NEXP];
#pragma unroll
        for (int e = 0; e < NEXP; e++) { p[e] = expf(lg[e] - mx); se += p[e]; }
        float inv = 1.f / se;
#pragma unroll
        for (int e = 0; e < NEXP; e++) { p[e] *= inv; g_probs[t*NEXP + e] = p[e]; }
        g_lse[t] = mx + logf(se);
        int i0 = 0;
#pragma unroll
        for (int e = 1; e < NEXP; e++) if (p[e] > p[i0]) i0 = e;
        int i1 = -1;
#pragma unroll
        for (int e = 0; e < NEXP; e++) {
            if (e == i0) continue;
            if (i1 < 0 || p[e] > p[i1]) i1 = e;
        }
        float s2 = p[i0] + p[i1];
        g_eids[t*2 + 0] = i0; g_eids[t*2 + 1] = i1;
        g_ew[t*2 + 0] = p[i0] / s2; g_ew[t*2 + 1] = p[i1] / s2;
    }
}

// ---------------- rank: exclusive prefix count per (k, expert) in token order ----------------
__global__ void __launch_bounds__(256) rank_kernel()
{
    int k = blockIdx.x >> 3;
    int e = blockIdx.x & 7;
    __shared__ int warp_sums[8];
    __shared__ int s_base;
    if (threadIdx.x == 0) s_base = 0;
    __syncthreads();
    int lane = threadIdx.x & 31, wid = threadIdx.x >> 5;
    for (int c = 0; c < N_TOK; c += 256) {
        int t = c + threadIdx.x;
        int flag = (g_eids[t*2 + k] == e) ? 1 : 0;
        unsigned m = __ballot_sync(0xffffffffu, flag);
        int pre = __popc(m & ((1u << lane) - 1u));
        if (lane == 31) warp_sums[wid] = pre + flag;
        __syncthreads();
        int wbase = 0;
        for (int w = 0; w < wid; w++) wbase += warp_sums[w];
        if (flag) g_rank[k*N_TOK + t] = s_base + wbase + pre;
        __syncthreads();
        if (threadIdx.x == 0) {
            int tot = 0;
            for (int w = 0; w < 8; w++) tot += warp_sums[w];
            s_base += tot;
        }
        __syncthreads();
    }
    if (threadIdx.x == 0) g_cnt[k*NEXP + e] = s_base;
}

// ---------------- clear token slots ----------------
__global__ void clear_tok_kernel()
{
    int i = blockIdx.x * 256 + threadIdx.x;
    if (i < TOT_SLOTS) { g_tok[i] = -1; g_wgt[i] = 0.f; }
}

// ---------------- build compact per-expert lists ----------------
__global__ void build_kernel()
{
    int t = blockIdx.x * 256 + threadIdx.x;
    if (t >= N_TOK) return;
#pragma unroll
    for (int k = 0; k < 2; k++) {
        int e = g_eids[t*2 + k];
        int r = g_rank[k*N_TOK + t];
        if (r < CAP) {
            int slot = e*SLOTS_PER_E + k*CAP + r;
            g_tok[slot] = t;
            g_wgt[slot] = g_ew[t*2 + k];
        }
    }
}

// ---------------- fused GEMM1 (fp16 mma + ldmatrix), 256x(64+64) tile ----------------
// grid: (FDIM/64, SLOTS_PER_E/256, NEXP), block 512, dyn smem
// B tile rows [0,64)=gate cols n0.., rows [64,128)=up cols n0..
__global__ void __launch_bounds__(512, 1) gemm1_h()
{
    int e = blockIdx.z;
    int m0 = blockIdx.y * 256;
    int seg = (m0 >= CAP) ? 1 : 0;
    int lim = min(g_cnt[seg*NEXP + e], CAP);
    if ((m0 - seg*CAP) >= lim) return;

    int n0 = blockIdx.x * 64;

    extern __shared__ __half smh[];
    unsigned smu = (unsigned)__cvta_generic_to_shared(smh);

    int tid = threadIdx.x;
    // A loading: 256 rows x 64B; 2 cp per thread
    int ar = tid >> 1;
    int hc = (tid & 1) * 16;
    int tok = g_tok[e*SLOTS_PER_E + m0 + ar];
    const __half* ap = g_xh + (size_t)max(tok, 0) * DDIM + hc;
    int abytes = (tok >= 0) ? 16 : 0;
    // B loading: 128 rows x 64B; 1 cp per thread
    int br = tid >> 2;
    int bo = (tid & 3) * 8;
    const __half* bp = (br < 64)
        ? (g_wgh + ((size_t)e*FDIM + n0 + br) * DDIM + bo)
        : (g_wuh + ((size_t)e*FDIM + n0 + (br - 64)) * DDIM + bo);

    const int KT = DDIM / BKH;      // 32

#pragma unroll
    for (int s = 0; s < STAGES-1; s++) {
        __half* sA = smh + s*STG_H;
        __half* sB = sA + ASTG;
        int k0 = s * BKH;
        cp_async16(sA + ar*HSTRIDE + hc,     ap + k0,     abytes);
        cp_async16(sA + ar*HSTRIDE + hc + 8, ap + k0 + 8, abytes);
        cp_async16(sB + br*HSTRIDE + bo,     bp + k0,     16);
        cp_commit();
    }

    float accg[4][2][4], accu[4][2][4];
#pragma unroll
    for (int a = 0; a < 4; a++)
#pragma unroll
        for (int b = 0; b < 2; b++)
#pragma unroll
            for (int c = 0; c < 4; c++) { accg[a][b][c] = 0.f; accu[a][b][c] = 0.f; }

    int wid = tid >> 5, lane = tid & 31;
    int wm = wid & 3, wn = wid >> 2;      // 4 m-warps(64 rows) x 4 n-warps(16 cols each mat)
    int g = lane >> 2, tg = lane & 3;
    int l8 = lane & 7, g1 = lane >> 3;

    unsigned aoff[4];
#pragma unroll
    for (int mt = 0; mt < 4; mt++)
        aoff[mt] = ((wm*64 + mt*16 + (g1 & 1)*8 + l8) * HSTRIDE + (g1 >> 1)*8) * 2;
    unsigned bgoff = ((wn*16 + (g1 >> 1)*8 + l8) * HSTRIDE + (g1 & 1)*8) * 2 + ASTG*2;
    unsigned buoff = ((64 + wn*16 + (g1 >> 1)*8 + l8) * HSTRIDE + (g1 & 1)*8) * 2 + ASTG*2;

    for (int kt = 0; kt < KT; kt++) {
        cp_wait();
        __syncthreads();
        int pf = kt + STAGES - 1;
        if (pf < KT) {
            int st = pf % STAGES;
            __half* sA = smh + st*STG_H;
            __half* sB = sA + ASTG;
            int k0 = pf * BKH;
            cp_async16(sA + ar*HSTRIDE + hc,     ap + k0,     abytes);
            cp_async16(sA + ar*HSTRIDE + hc + 8, ap + k0 + 8, abytes);
            cp_async16(sB + br*HSTRIDE + bo,     bp + k0,     16);
        }
        cp_commit();
        unsigned stOff = smu + (kt % STAGES)*(STG_H*2);
#pragma unroll
        for (int kk = 0; kk < 2; kk++) {
            unsigned kb = kk * 32;
            unsigned af[4][4], bg[4], bu[4];
#pragma unroll
            for (int mt = 0; mt < 4; mt++) ldsm_x4(af[mt], stOff + aoff[mt] + kb);
            ldsm_x4(bg, stOff + bgoff + kb);
            ldsm_x4(bu, stOff + buoff + kb);
#pragma unroll
            for (int mt = 0; mt < 4; mt++) {
                mma_f16(accg[mt][0], af[mt], &bg[0]);
                mma_f16(accg[mt][1], af[mt], &bg[2]);
                mma_f16(accu[mt][0], af[mt], &bu[0]);
                mma_f16(accu[mt][1], af[mt], &bu[2]);
            }
        }
    }

    // epilogue: silu(g)*u -> fp16 store
#pragma unroll
    for (int mt = 0; mt < 4; mt++) {
        int r0 = m0 + wm*64 + mt*16 + g;
        __half* row0 = g_hh + ((size_t)e*SLOTS_PER_E + r0) * FDIM;
        __half* row1 = g_hh + ((size_t)e*SLOTS_PER_E + r0 + 8) * FDIM;
#pragma unroll
        for (int nt = 0; nt < 2; nt++) {
            int c0 = n0 + wn*16 + nt*8 + tg*2;
            float2 v0, v1;
            v0.x = silu_mul(accg[mt][nt][0], accu[mt][nt][0]);
            v0.y = silu_mul(accg[mt][nt][1], accu[mt][nt][1]);
            v1.x = silu_mul(accg[mt][nt][2], accu[mt][nt][2]);
            v1.y = silu_mul(accg[mt][nt][3], accu[mt][nt][3]);
            *(__half2*)(row0 + c0) = __float22half2_rn(v0);
            *(__half2*)(row1 + c0) = __float22half2_rn(v1);
        }
    }
}

// ---------------- GEMM2 (fp16 mma + ldmatrix), 256x128 tile: y = act @ Wo^T ----------------
// grid: (DDIM/128, SLOTS_PER_E/256, NEXP), block 512, dyn smem
__global__ void __launch_bounds__(512, 1) gemm2_h()
{
    int e = blockIdx.z;
    int m0 = blockIdx.y * 256;
    int seg = (m0 >= CAP) ? 1 : 0;
    int lim = min(g_cnt[seg*NEXP + e], CAP);
    if ((m0 - seg*CAP) >= lim) return;

    int n0 = blockIdx.x * 128;

    extern __shared__ __half smh[];
    unsigned smu = (unsigned)__cvta_generic_to_shared(smh);

    int tid = threadIdx.x;
    int ar = tid >> 1;
    int hc = (tid & 1) * 16;
    const __half* ap = g_hh + ((size_t)e*SLOTS_PER_E + m0 + ar) * FDIM + hc;
    int br = tid >> 2;
    int bo = (tid & 3) * 8;
    const __half* bp = g_woh + ((size_t)e*DDIM + n0 + br) * FDIM + bo;

    const int KT = FDIM / BKH;      // 128

#pragma unroll
    for (int s = 0; s < STAGES-1; s++) {
        __half* sA = smh + s*STG_H;
        __half* sB = sA + ASTG;
        int k0 = s * BKH;
        cp_async16(sA + ar*HSTRIDE + hc,     ap + k0,     16);
        cp_async16(sA + ar*HSTRIDE + hc + 8, ap + k0 + 8, 16);
        cp_async16(sB + br*HSTRIDE + bo,     bp + k0,     16);
        cp_commit();
    }

    float acc[4][4][4];
#pragma unroll
    for (int a = 0; a < 4; a++)
#pragma unroll
        for (int b = 0; b < 4; b++)
#pragma unroll
            for (int c = 0; c < 4; c++) acc[a][b][c] = 0.f;

    int wid = tid >> 5, lane = tid & 31;
    int wm = wid & 3, wn = wid >> 2;      // 4 m-warps(64 rows) x 4 n-warps(32 cols)
    int g = lane >> 2, tg = lane & 3;
    int l8 = lane & 7, g1 = lane >> 3;

    unsigned aoff[4];
#pragma unroll
    for (int mt = 0; mt < 4; mt++)
        aoff[mt] = ((wm*64 + mt*16 + (g1 & 1)*8 + l8) * HSTRIDE + (g1 >> 1)*8) * 2;
    unsigned boff[2];
#pragma unroll
    for (int p = 0; p < 2; p++)
        boff[p] = ((wn*32 + p*16 + (g1 >> 1)*8 + l8) * HSTRIDE + (g1 & 1)*8) * 2 + ASTG*2;

    for (int kt = 0; kt < KT; kt++) {
        cp_wait();
        __syncthreads();
        int pf = kt + STAGES - 1;
        if (pf < KT) {
            int st = pf % STAGES;
            __half* sA = smh + st*STG_H;
            __half* sB = sA + ASTG;
            int k0 = pf * BKH;
            cp_async16(sA + ar*HSTRIDE + hc,     ap + k0,     16);
            cp_async16(sA + ar*HSTRIDE + hc + 8, ap + k0 + 8, 16);
            cp_async16(sB + br*HSTRIDE + bo,     bp + k0,     16);
        }
        cp_commit();
        unsigned stOff = smu + (kt % STAGES)*(STG_H*2);
#pragma unroll
        for (int kk = 0; kk < 2; kk++) {
            unsigned kb = kk * 32;
            unsigned af[4][4], b2[2][4];
#pragma unroll
            for (int mt = 0; mt < 4; mt++) ldsm_x4(af[mt], stOff + aoff[mt] + kb);
#pragma unroll
            for (int p = 0; p < 2; p++) ldsm_x4(b2[p], stOff + boff[p] + kb);
#pragma unroll
            for (int mt = 0; mt < 4; mt++)
#pragma unroll
                for (int p = 0; p < 2; p++) {
                    mma_f16(acc[mt][2*p+0], af[mt], &b2[p][0]);
                    mma_f16(acc[mt][2*p+1], af[mt], &b2[p][2]);
                }
        }
    }

#pragma unroll
    for (int mt = 0; mt < 4; mt++) {
        int r0 = m0 + wm*64 + mt*16 + g;
        int slot0 = e*SLOTS_PER_E + r0;
        int t0 = g_tok[slot0];
        int t1 = g_tok[slot0 + 8];
        float w0 = g_wgt[slot0];
        float w1 = g_wgt[slot0 + 8];
#pragma unroll
        for (int nt = 0; nt < 4; nt++) {
            int c0 = n0 + wn*32 + nt*8 + tg*2;
            if (t0 >= 0) {
                float2 v = make_float2(acc[mt][nt][0]*w0, acc[mt][nt][1]*w0);
                *(float2*)&g_ybuf[((size_t)t0*2 + seg)*DDIM + c0] = v;
            }
            if (t1 >= 0) {
                float2 v = make_float2(acc[mt][nt][2]*w1, acc[mt][nt][3]*w1);
                *(float2*)&g_ybuf[((size_t)t1*2 + seg)*DDIM + c0] = v;
            }
        }
    }
}

// ---------------- combine: out[t] = ybuf[t,0] + ybuf[t,1] (validity-masked) ----------------
__global__ void __launch_bounds__(256) combine_kernel(float* __restrict__ out)
{
    int t = blockIdx.x;
    bool v0 = g_rank[t] < CAP;
    bool v1 = g_rank[N_TOK + t] < CAP;
    const float4* y0 = (const float4*)(g_ybuf + (size_t)t * 2 * DDIM);
    const float4* y1 = y0 + DDIM/4;
    float4 a = v0 ? y0[threadIdx.x] : make_float4(0.f,0.f,0.f,0.f);
    float4 b = v1 ? y1[threadIdx.x] : make_float4(0.f,0.f,0.f,0.f);
    float4 r = make_float4(a.x+b.x, a.y+b.y, a.z+b.z, a.w+b.w);
    ((float4*)(out + (size_t)t * DDIM))[threadIdx.x] = r;
}

// ---------------- aux loss: deterministic tree reduction ----------------
__global__ void __launch_bounds__(1024) aux_kernel(float* __restrict__ out_aux)
{
    __shared__ float sb[1024];
    __shared__ float res[9];
    int tid = threadIdx.x;
    float pacc[NEXP];
#pragma unroll
    for (int e = 0; e < NEXP; e++) pacc[e] = 0.f;
    float zacc = 0.f;
    for (int i = 0; i < N_TOK/1024; i++) {
        int t = tid * (N_TOK/1024) + i;
        const float* pr = g_probs + (size_t)t * NEXP;
#pragma unroll
        for (int e = 0; e < NEXP; e++) pacc[e] += pr[e];
        float l = g_lse[t];
        zacc += l * l;
    }
    for (int e = 0; e < NEXP; e++) {
        sb[tid] = pacc[e];
        __syncthreads();
        for (int s = 512; s > 0; s >>= 1) {
            if (tid < s) sb[tid] += sb[tid + s];
            __syncthreads();
        }
        if (tid == 0) res[e] = sb[0];
        __syncthreads();
    }
    sb[tid] = zacc;
    __syncthreads();
    for (int s = 512; s > 0; s >>= 1) {
        if (tid < s) sb[tid] += sb[tid + s];
        __syncthreads();
    }
    if (tid == 0) res[8] = sb[0];
    __syncthreads();
    if (tid == 0) {
        float lb = 0.f;
#pragma unroll
        for (int e = 0; e < NEXP; e++) {
            float density = (float)(g_cnt[e] + g_cnt[NEXP + e]) / (float)(N_TOK * 2);
            float mean_p = res[e] / (float)N_TOK;
            lb += density * mean_p;
        }
        lb *= 0.01f * (float)NEXP;
        float z = 0.001f * (res[8] / (float)N_TOK);
        out_aux[0] = lb + z;
    }
}

// ---------------- launch ----------------
extern "C" void kernel_launch(void* const* d_in, const int* in_sizes, int n_in,
                              void* d_out, int out_size)
{
    const float* x       = (const float*)d_in[0];
    const float* gate_w  = (const float*)d_in[1];
    const float* wi_gate = (const float*)d_in[2];
    const float* wi_up   = (const float*)d_in[3];
    const float* wo      = (const float*)d_in[4];
    float* out = (float*)d_out;

    static bool s_attr = false;
    if (!s_attr) {
        cudaFuncSetAttribute(gemm1_h, cudaFuncAttributeMaxDynamicSharedMemorySize, SMEM_BYTES);
        cudaFuncSetAttribute(gemm2_h, cudaFuncAttributeMaxDynamicSharedMemorySize, SMEM_BYTES);
        s_attr = true;
    }

    // launch order chosen so gemm1_h is the 6th launch (ncu -s 5 -c 1 target)
    h_convert_all<<<2048, 256>>>((const float2*)x, (const float2*)wi_gate,
                                 (const float2*)wi_up, (const float2*)wo);
    router_kernel<<<N_TOK, 256>>>(x, gate_w);
    rank_kernel<<<16, 256>>>();
    clear_tok_kernel<<<(TOT_SLOTS + 255)/256, 256>>>();
    build_kernel<<<N_TOK/256, 256>>>();

    gemm1_h<<<dim3(FDIM/64, SLOTS_PER_E/256, NEXP), 512, SMEM_BYTES>>>();
    gemm2_h<<<dim3(DDIM/128, SLOTS_PER_E/256, NEXP), 512, SMEM_BYTES>>>();

    combine_kernel<<<N_TOK, 256>>>(out);

    if (out_size > N_TOK * DDIM) {
        aux_kernel<<<1, 1024>>>(out + (size_t)N_TOK * DDIM);
    }
}